// round 13
// baseline (speedup 1.0000x reference)
#include <cuda_runtime.h>
#include <cuda_fp16.h>
#include <cstdint>
#include <string.h>
#include <math.h>

// Problem constants
#define SEQ 2048
#define DIM 2048
#define NH  16
#define DK  128

// ------------------------------------------------------------------
// Scratch (device globals)
// ------------------------------------------------------------------
__device__ __half g_a[SEQ * DIM];             // A operand (x, then att), fp16
__device__ __half g_wt[4u * DIM * DIM];       // W^T per matrix, K-major, fp16
__device__ __half g_q[NH * SEQ * DK];         // Q fp16 (1/sqrt(dk) folded)
__device__ __half g_k[NH * SEQ * DK];         // K fp16
__device__ __half g_v[NH * SEQ * DK];         // V fp16 (row-major, trans at ldmatrix)

// ------------------------------------------------------------------
// Baseline-PTX helpers (sm_80-level)
// ------------------------------------------------------------------
__device__ __forceinline__ uint32_t smem_u32(const void* p) {
    uint32_t a;
    asm("{ .reg .u64 t; cvta.to.shared.u64 t, %1; cvt.u32.u64 %0, t; }" : "=r"(a) : "l"(p));
    return a;
}

#define CP_ASYNC16(sm, gp) \
    asm volatile("cp.async.cg.shared.global [%0], [%1], 16;" :: "r"(sm), "l"(gp))
#define CP_COMMIT() asm volatile("cp.async.commit_group;" ::: "memory")
#define CP_WAIT1()  asm volatile("cp.async.wait_group 1;" ::: "memory")
#define CP_WAIT0()  asm volatile("cp.async.wait_group 0;" ::: "memory")

#define LDSM_X4(r0, r1, r2, r3, addr) \
    asm volatile("ldmatrix.sync.aligned.m8n8.x4.shared.b16 {%0,%1,%2,%3}, [%4];" \
                 : "=r"(r0), "=r"(r1), "=r"(r2), "=r"(r3) : "r"(addr))

#define LDSM_X4_T(r0, r1, r2, r3, addr) \
    asm volatile("ldmatrix.sync.aligned.m8n8.x4.trans.shared.b16 {%0,%1,%2,%3}, [%4];" \
                 : "=r"(r0), "=r"(r1), "=r"(r2), "=r"(r3) : "r"(addr))

#define MMA16816(c, a, b) \
    asm volatile("mma.sync.aligned.m16n8k16.row.col.f32.f16.f16.f32 " \
                 "{%0,%1,%2,%3}, {%4,%5,%6,%7}, {%8,%9}, {%0,%1,%2,%3};" \
                 : "+f"((c)[0]), "+f"((c)[1]), "+f"((c)[2]), "+f"((c)[3]) \
                 : "r"((a)[0]), "r"((a)[1]), "r"((a)[2]), "r"((a)[3]), \
                   "r"((b)[0]), "r"((b)[1]))

__device__ __forceinline__ uint32_t h2u(__half2 v) {
    uint32_t u; memcpy(&u, &v, 4); return u;
}

// ------------------------------------------------------------------
// Fused conversion kernel (single launch):
//   z=0..3: W[K,N] -> W^T [N,K] fp16 (Wq scale folded in)
//   z=4   : x fp32 -> g_a fp16 (no transpose)
// ------------------------------------------------------------------
__global__ __launch_bounds__(256) void convert_all(
    const float* __restrict__ Wq, const float* __restrict__ Wk,
    const float* __restrict__ Wv, const float* __restrict__ Wo,
    const float* __restrict__ x)
{
    int z = blockIdx.z;
    int tx = threadIdx.x, ty = threadIdx.y;   // (32, 8)

    if (z == 4) {
        // straight cast: 32x32 tile, 4 rows per thread
        int c0 = blockIdx.x * 32, r0 = blockIdx.y * 32;
#pragma unroll
        for (int tt = 0; tt < 4; ++tt) {
            int r = r0 + ty + 8 * tt;
            g_a[(size_t)r * DIM + c0 + tx] =
                __float2half_rn(x[(size_t)r * DIM + c0 + tx]);
        }
        return;
    }

    __shared__ float tile[32][33];
    const float* W = (z == 0) ? Wq : (z == 1) ? Wk : (z == 2) ? Wv : Wo;
    float scale = (z == 0) ? 0.08838834764831845f : 1.0f;
    __half* t = g_wt + (size_t)z * DIM * DIM;

    int n0 = blockIdx.x * 32, k0 = blockIdx.y * 32;
#pragma unroll
    for (int tt = 0; tt < 4; ++tt)
        tile[ty + 8 * tt][tx] = W[(size_t)(k0 + ty + 8 * tt) * DIM + n0 + tx] * scale;
    __syncthreads();
#pragma unroll
    for (int tt = 0; tt < 4; ++tt) {
        int r = ty + 8 * tt;
        t[(size_t)(n0 + r) * DIM + k0 + tx] = __float2half_rn(tile[tx][r]);
    }
}

// ------------------------------------------------------------------
// mma.sync fp16 GEMM (1-term): out = A @ B^T + bias
// CTA 128x128, KC=64, cp.async double buffer, 2 CTAs/SM.
// ------------------------------------------------------------------
#define TMM 128
#define TNN 128
#define KC 64
#define NCHUNK (DIM / KC)
#define LSTRIDE 144
#define TILE_B (128 * LSTRIDE)      // 18432
#define OFF_A 0
#define OFF_B (1 * TILE_B)
#define STAGE_B (2 * TILE_B)        // 36864
#define GEMM_SMEM (2 * STAGE_B)     // 73728

__device__ __forceinline__ void load_chunk(
    uint32_t sbase, const __half* __restrict__ A, const __half* __restrict__ B,
    int row0, int col0, int k0, int tid)
{
    const int col16 = tid & 7;
    const int rb    = tid >> 3;
    const int kg    = k0 + col16 * 8;
#pragma unroll
    for (int t = 0; t < 4; ++t) {
        int r = rb + t * 32;
        uint32_t so = r * LSTRIDE + col16 * 16;
        CP_ASYNC16(sbase + OFF_A + so, A + (size_t)(row0 + r) * DIM + kg);
        CP_ASYNC16(sbase + OFF_B + so, B + (size_t)(col0 + r) * DIM + kg);
    }
}

// mode 0: fp32 [S][DIM]; mode 2: fp16 scatter [H][S][DK]
__device__ __forceinline__ void gemm_tc_body(
    const __half* __restrict__ A, const __half* __restrict__ B,
    const float* __restrict__ bias, float bscale,
    float* __restrict__ outp, __half* __restrict__ ohi, int mode)
{
    extern __shared__ char smg[];
    const int tid  = threadIdx.x;
    const int wid  = tid >> 5;
    const int lane = tid & 31;
    const int row0 = blockIdx.y * TMM;
    const int col0 = blockIdx.x * TNN;
    const int wm   = (wid & 3) * 32;
    const int wn   = (wid >> 2) * 64;
    const uint32_t sb = smem_u32(smg);

    float c[2][8][4];
#pragma unroll
    for (int mt = 0; mt < 2; ++mt)
#pragma unroll
        for (int nt = 0; nt < 8; ++nt)
#pragma unroll
            for (int j = 0; j < 4; ++j) c[mt][nt][j] = 0.0f;

    const uint32_t a_off = (wm + (lane & 15)) * LSTRIDE + (lane >> 4) * 16;
    const uint32_t b_row = wn + (lane & 7) + ((lane >> 4) & 1) * 8;
    const uint32_t b_off = b_row * LSTRIDE + ((lane >> 3) & 1) * 16;

    load_chunk(sb, A, B, row0, col0, 0, tid);
    CP_COMMIT();

    for (int ch = 0; ch < NCHUNK; ++ch) {
        const uint32_t stage = sb + (ch & 1) * STAGE_B;
        if (ch + 1 < NCHUNK) {
            load_chunk(sb + ((ch + 1) & 1) * STAGE_B, A, B, row0, col0, (ch + 1) * KC, tid);
            CP_COMMIT();
            CP_WAIT1();
        } else {
            CP_WAIT0();
        }
        __syncthreads();

#pragma unroll
        for (int ks = 0; ks < 4; ++ks) {
            const uint32_t kb = ks * 32;
            uint32_t a[2][4];
#pragma unroll
            for (int mt = 0; mt < 2; ++mt) {
                uint32_t ad = stage + (uint32_t)(mt * 16 * LSTRIDE) + a_off + kb;
                LDSM_X4(a[mt][0], a[mt][1], a[mt][2], a[mt][3], ad + OFF_A);
            }
            uint32_t b[8][2];
#pragma unroll
            for (int q = 0; q < 4; ++q) {
                uint32_t bd = stage + (uint32_t)(q * 16 * LSTRIDE) + b_off + kb;
                LDSM_X4(b[2 * q][0], b[2 * q][1], b[2 * q + 1][0], b[2 * q + 1][1],
                        bd + OFF_B);
            }
#pragma unroll
            for (int mt = 0; mt < 2; ++mt)
#pragma unroll
                for (int nt = 0; nt < 8; ++nt)
                    MMA16816(c[mt][nt], a[mt], b[nt]);
        }
        __syncthreads();
    }

#pragma unroll
    for (int mt = 0; mt < 2; ++mt) {
#pragma unroll
        for (int nt = 0; nt < 8; ++nt) {
            int cg = col0 + wn + nt * 8 + (lane & 3) * 2;
            float b0 = bias[cg] * bscale;
            float b1 = bias[cg + 1] * bscale;
            int r0 = row0 + wm + mt * 16 + (lane >> 2);
#pragma unroll
            for (int hh = 0; hh < 2; ++hh) {
                int r = r0 + hh * 8;
                float v0 = c[mt][nt][2 * hh + 0] + b0;
                float v1 = c[mt][nt][2 * hh + 1] + b1;
                if (mode == 0) {
                    float* ob = outp + (size_t)r * DIM + cg;
                    ob[0] = v0; ob[1] = v1;
                } else {
                    int hd = cg >> 7, d0 = cg & 127;
                    size_t base = ((size_t)hd * SEQ + r) * DK + d0;
                    *(__half2*)(ohi + base) =
                        __halves2half2(__float2half_rn(v0), __float2half_rn(v1));
                }
            }
        }
    }
}

__global__ __launch_bounds__(256, 2) void qkv_tc(
    const float* __restrict__ bq, const float* __restrict__ bk, const float* __restrict__ bvv)
{
    int z = blockIdx.z;
    const __half* W = g_wt + (size_t)z * DIM * DIM;
    const float* bias = (z == 0) ? bq : (z == 1) ? bk : bvv;
    __half* outp = (z == 0) ? g_q : (z == 1) ? g_k : g_v;
    float bscale = (z == 0) ? 0.08838834764831845f : 1.0f;
    gemm_tc_body(g_a, W, bias, bscale, nullptr, outp, 2);
}

__global__ __launch_bounds__(256, 2) void out_tc(const float* __restrict__ bo, float* __restrict__ out)
{
    gemm_tc_body(g_a, g_wt + (size_t)3 * DIM * DIM, bo, 1.0f, out, nullptr, 0);
}

// ------------------------------------------------------------------
// mma.sync fp16 causal flash attention — cross-tile software pipeline.
// Q, K, V, P all fp16 (1-term QK, 1-term PV). Q fragments register-
// resident across tiles. Per tile jt: QK_jt, then deferred PV_{jt-1},
// then softmax_jt + pack. 4-stage KV ring, one __syncthreads per tile.
// CTA: 128 q-rows x 1 head, 256 threads (8 warps x 16 rows).
// ------------------------------------------------------------------
#define QT 128
#define KT 64
#define QSTR 272                      // 256B payload + 16B pad
#define QB 0                          // Q: 128 rows x QSTR = 34816
#define QB_TOT (128 * QSTR)           // 34816
#define SK 0                          // K: 64 rows x QSTR = 17408
#define SV (64 * QSTR)                // V: 64 rows x QSTR = 17408
#define STAGE_SZ (2 * 64 * QSTR)      // 34816 per KV stage
#define NSTAGE 4
#define ATTN_SMEM (QB_TOT + NSTAGE * STAGE_SZ)   // 174080

__device__ __forceinline__ void attn_load_kv(uint32_t st, int h, int kv0, int tid)
{
    const __half* kh = g_k + ((size_t)h * SEQ + kv0) * DK;
    const __half* vh = g_v + ((size_t)h * SEQ + kv0) * DK;
    int r = tid >> 2;                 // 0..63
#pragma unroll
    for (int i = 0; i < 4; ++i) {
        int u = (tid & 3) * 4 + i;
        CP_ASYNC16(st + SK + r * QSTR + u * 16, kh + (size_t)r * DK + u * 8);
        CP_ASYNC16(st + SV + r * QSTR + u * 16, vh + (size_t)r * DK + u * 8);
    }
}

__global__ __launch_bounds__(256, 1) void attn_mma()
{
    extern __shared__ char sma[];
    const uint32_t sb = smem_u32(sma);
    const int tid  = threadIdx.x;
    const int wid  = tid >> 5;
    const int lane = tid & 31;
    const int h    = blockIdx.y;
    const int qi   = 15 - blockIdx.x;      // heavy tiles first
    const int q0   = qi * QT;
    const int ntiles = 2 * (qi + 1);

    // prologue: Q tile + stage 0 KV
    {
        const __half* qh = g_q + ((size_t)h * SEQ + q0) * DK;
        int r = tid >> 1;
#pragma unroll
        for (int i = 0; i < 8; ++i) {
            int u = (tid & 1) * 8 + i;
            CP_ASYNC16(sb + QB + r * QSTR + u * 16, qh + (size_t)r * DK + u * 8);
        }
        attn_load_kv(sb + QB_TOT, h, 0, tid);
        CP_COMMIT();
    }

    // per-lane fragment address components
    const uint32_t a_off  = (wid * 16 + (lane & 15)) * QSTR + (lane >> 4) * 16;
    const uint32_t bk_off = ((lane & 7) + ((lane >> 4) & 1) * 8) * QSTR + ((lane >> 3) & 1) * 16;
    // V via ldmatrix.trans: tiles (k0-7,d0)(k8-15,d0)(k0-7,d1)(k8-15,d1)
    const uint32_t bv_off = ((lane & 7) + ((lane >> 3) & 1) * 8) * QSTR + ((lane >> 4) & 1) * 16;

    const int row0_abs = q0 + wid * 16 + (lane >> 2);
    const int rowmax   = q0 + wid * 16 + 15;

    float o[16][4];
#pragma unroll
    for (int nt = 0; nt < 16; ++nt)
#pragma unroll
        for (int j = 0; j < 4; ++j) o[nt][j] = 0.0f;
    float m0 = -1e4f, m1 = -1e4f, l0 = 0.0f, l1 = 0.0f;

    // register-resident Q fragments (loaded once at jt==0)
    uint32_t qa[8][4];
    // deferred-PV state (P fp16, 1-term)
    uint32_t aph[4][4];
    uint32_t prev_st = 0;
    int have_prev = 0;

    for (int jt = 0; jt < ntiles; ++jt) {
        if (jt + 1 < ntiles) {
            attn_load_kv(sb + QB_TOT + ((jt + 1) & (NSTAGE - 1)) * STAGE_SZ,
                         h, (jt + 1) * KT, tid);
            CP_COMMIT();
            CP_WAIT1();
        } else {
            CP_WAIT0();
        }
        __syncthreads();   // single barrier per tile (4-stage ring)

        if (jt == 0) {
            // Q smem is final now; hoist all Q fragments into registers
#pragma unroll
            for (int ks = 0; ks < 8; ++ks)
                LDSM_X4(qa[ks][0], qa[ks][1], qa[ks][2], qa[ks][3],
                        sb + QB + a_off + ks * 32);
        }

        const int kv0 = jt * KT;
        const int active = (kv0 <= rowmax);
        const uint32_t st = sb + QB_TOT + (jt & (NSTAGE - 1)) * STAGE_SZ;

        // ---- issue QK_jt (Q from registers) ----
        float s[8][4];
        if (active) {
#pragma unroll
            for (int nt = 0; nt < 8; ++nt)
#pragma unroll
                for (int j = 0; j < 4; ++j) s[nt][j] = 0.0f;
#pragma unroll
            for (int ks = 0; ks < 8; ++ks) {
                uint32_t bh[8][2];
#pragma unroll
                for (int q = 0; q < 4; ++q) {
                    uint32_t ba = st + SK + bk_off + q * (16 * QSTR) + ks * 32;
                    LDSM_X4(bh[2 * q][0], bh[2 * q][1], bh[2 * q + 1][0], bh[2 * q + 1][1], ba);
                }
#pragma unroll
                for (int nt = 0; nt < 8; ++nt) MMA16816(s[nt], qa[ks], bh[nt]);
            }
        }

        // ---- deferred PV_{jt-1}: overlaps the QK->softmax dependency ----
        if (have_prev) {
#pragma unroll
            for (int kp = 0; kp < 4; ++kp) {
#pragma unroll
                for (int p = 0; p < 8; ++p) {
                    uint32_t r0, r1, r2, r3;
                    LDSM_X4_T(r0, r1, r2, r3,
                              prev_st + SV + bv_off + kp * (16 * QSTR) + p * 32);
                    uint32_t b01[2] = {r0, r1};
                    uint32_t b23[2] = {r2, r3};
                    MMA16816(o[2 * p + 0], aph[kp], b01);
                    MMA16816(o[2 * p + 1], aph[kp], b23);
                }
            }
            have_prev = 0;
        }

        if (active) {
            // ---- causal mask ----
            if (kv0 + KT - 1 > q0 + wid * 16) {
#pragma unroll
                for (int nt = 0; nt < 8; ++nt) {
                    int cb = kv0 + nt * 8 + (lane & 3) * 2;
#pragma unroll
                    for (int j = 0; j < 4; ++j) {
                        int col = cb + (j & 1);
                        int row = row0_abs + (j >> 1) * 8;
                        if (col > row) s[nt][j] = -1e30f;
                    }
                }
            }

            // ---- online softmax ----
            float tm0 = -1e30f, tm1 = -1e30f;
#pragma unroll
            for (int nt = 0; nt < 8; ++nt) {
                tm0 = fmaxf(tm0, fmaxf(s[nt][0], s[nt][1]));
                tm1 = fmaxf(tm1, fmaxf(s[nt][2], s[nt][3]));
            }
            tm0 = fmaxf(tm0, __shfl_xor_sync(0xffffffffu, tm0, 1));
            tm0 = fmaxf(tm0, __shfl_xor_sync(0xffffffffu, tm0, 2));
            tm1 = fmaxf(tm1, __shfl_xor_sync(0xffffffffu, tm1, 1));
            tm1 = fmaxf(tm1, __shfl_xor_sync(0xffffffffu, tm1, 2));
            float mn0 = fmaxf(fmaxf(m0, tm0), -1e4f);
            float mn1 = fmaxf(fmaxf(m1, tm1), -1e4f);
            float al0 = __expf(m0 - mn0), al1 = __expf(m1 - mn1);
            m0 = mn0; m1 = mn1;
            float ls0 = 0.0f, ls1 = 0.0f;
#pragma unroll
            for (int nt = 0; nt < 8; ++nt) {
                s[nt][0] = __expf(s[nt][0] - mn0);
                s[nt][1] = __expf(s[nt][1] - mn0);
                s[nt][2] = __expf(s[nt][2] - mn1);
                s[nt][3] = __expf(s[nt][3] - mn1);
                ls0 += s[nt][0] + s[nt][1];
                ls1 += s[nt][2] + s[nt][3];
            }
            l0 = l0 * al0 + ls0;
            l1 = l1 * al1 + ls1;
#pragma unroll
            for (int nt = 0; nt < 16; ++nt) {
                o[nt][0] *= al0; o[nt][1] *= al0;
                o[nt][2] *= al1; o[nt][3] *= al1;
            }

            // ---- pack P_jt into PV A-frags (fp16, 1-term), defer the MMAs ----
#pragma unroll
            for (int pr = 0; pr < 4; ++pr) {
#pragma unroll
                for (int half = 0; half < 2; ++half) {
                    int nt = 2 * pr + half;
                    aph[pr][2 * half + 0] =
                        h2u(__halves2half2(__float2half_rn(s[nt][0]),
                                           __float2half_rn(s[nt][1])));
                    aph[pr][2 * half + 1] =
                        h2u(__halves2half2(__float2half_rn(s[nt][2]),
                                           __float2half_rn(s[nt][3])));
                }
            }
            prev_st = st;
            have_prev = 1;
        }
    }

    // ---- drain last deferred PV ----
    if (have_prev) {
#pragma unroll
        for (int kp = 0; kp < 4; ++kp) {
#pragma unroll
            for (int p = 0; p < 8; ++p) {
                uint32_t r0, r1, r2, r3;
                LDSM_X4_T(r0, r1, r2, r3,
                          prev_st + SV + bv_off + kp * (16 * QSTR) + p * 32);
                uint32_t b01[2] = {r0, r1};
                uint32_t b23[2] = {r2, r3};
                MMA16816(o[2 * p + 0], aph[kp], b01);
                MMA16816(o[2 * p + 1], aph[kp], b23);
            }
        }
    }

    // ---- epilogue: normalize, cast fp16, write att into A operand ----
    l0 += __shfl_xor_sync(0xffffffffu, l0, 1);
    l0 += __shfl_xor_sync(0xffffffffu, l0, 2);
    l1 += __shfl_xor_sync(0xffffffffu, l1, 1);
    l1 += __shfl_xor_sync(0xffffffffu, l1, 2);
    float inv0 = 1.0f / l0, inv1 = 1.0f / l1;

    const int r0 = row0_abs;
    const int r1 = row0_abs + 8;
#pragma unroll
    for (int nt = 0; nt < 16; ++nt) {
        int d = h * DK + nt * 8 + (lane & 3) * 2;
        *(__half2*)(g_a + (size_t)r0 * DIM + d) =
            __halves2half2(__float2half_rn(o[nt][0] * inv0),
                           __float2half_rn(o[nt][1] * inv0));
        *(__half2*)(g_a + (size_t)r1 * DIM + d) =
            __halves2half2(__float2half_rn(o[nt][2] * inv1),
                           __float2half_rn(o[nt][3] * inv1));
    }
}

// ------------------------------------------------------------------
// Launch
// ------------------------------------------------------------------
extern "C" void kernel_launch(void* const* d_in, const int* in_sizes, int n_in,
                              void* d_out, int out_size)
{
    const float* x  = (const float*)d_in[0];
    const float* Wq = (const float*)d_in[1];
    const float* bq = (const float*)d_in[2];
    const float* Wk = (const float*)d_in[3];
    const float* bk = (const float*)d_in[4];
    const float* Wv = (const float*)d_in[5];
    const float* bv = (const float*)d_in[6];
    const float* Wo = (const float*)d_in[7];
    const float* bo = (const float*)d_in[8];
    float* out = (float*)d_out;

    cudaFuncSetAttribute(qkv_tc, cudaFuncAttributeMaxDynamicSharedMemorySize, GEMM_SMEM);
    cudaFuncSetAttribute(out_tc, cudaFuncAttributeMaxDynamicSharedMemorySize, GEMM_SMEM);
    cudaFuncSetAttribute(attn_mma, cudaFuncAttributeMaxDynamicSharedMemorySize, ATTN_SMEM);

    dim3 tblk(32, 8);

    // 1) all conversions in ONE launch (4x W^T + x cast)
    convert_all<<<dim3(DIM / 32, DIM / 32, 5), tblk>>>(Wq, Wk, Wv, Wo, x);

    // 2) Q/K/V projections (all 1-term fp16)
    qkv_tc<<<dim3(DIM / TNN, SEQ / TMM, 3), 256, GEMM_SMEM>>>(bq, bk, bv);

    // 3) tensor-core causal flash attention (deferred-PV pipeline)
    attn_mma<<<dim3(SEQ / QT, NH), 256, ATTN_SMEM>>>();

    // 4) output projection (1-term)
    out_tc<<<dim3(DIM / TNN, SEQ / TMM), 256, GEMM_SMEM>>>(bo, out);
}

// round 14
// speedup vs baseline: 1.5216x; 1.5216x over previous
#include <cuda_runtime.h>
#include <cuda_fp16.h>
#include <cstdint>
#include <string.h>
#include <math.h>

// Problem constants
#define SEQ 2048
#define DIM 2048
#define NH  16
#define DK  128

// ------------------------------------------------------------------
// Scratch (device globals)
// ------------------------------------------------------------------
__device__ __half g_a[SEQ * DIM];             // A operand (x, then att), fp16
__device__ __half g_wt[4u * DIM * DIM];       // W^T per matrix, K-major, fp16
__device__ __half g_q[NH * SEQ * DK];         // Q fp16 (1/sqrt(dk) folded)
__device__ __half g_k[NH * SEQ * DK];         // K fp16
__device__ __half g_v[NH * SEQ * DK];         // V fp16 (row-major, trans at ldmatrix)

// ------------------------------------------------------------------
// Baseline-PTX helpers (sm_80-level)
// ------------------------------------------------------------------
__device__ __forceinline__ uint32_t smem_u32(const void* p) {
    uint32_t a;
    asm("{ .reg .u64 t; cvta.to.shared.u64 t, %1; cvt.u32.u64 %0, t; }" : "=r"(a) : "l"(p));
    return a;
}

#define CP_ASYNC16(sm, gp) \
    asm volatile("cp.async.cg.shared.global [%0], [%1], 16;" :: "r"(sm), "l"(gp))
#define CP_COMMIT() asm volatile("cp.async.commit_group;" ::: "memory")
#define CP_WAIT1()  asm volatile("cp.async.wait_group 1;" ::: "memory")
#define CP_WAIT0()  asm volatile("cp.async.wait_group 0;" ::: "memory")

#define LDSM_X4(r0, r1, r2, r3, addr) \
    asm volatile("ldmatrix.sync.aligned.m8n8.x4.shared.b16 {%0,%1,%2,%3}, [%4];" \
                 : "=r"(r0), "=r"(r1), "=r"(r2), "=r"(r3) : "r"(addr))

#define LDSM_X4_T(r0, r1, r2, r3, addr) \
    asm volatile("ldmatrix.sync.aligned.m8n8.x4.trans.shared.b16 {%0,%1,%2,%3}, [%4];" \
                 : "=r"(r0), "=r"(r1), "=r"(r2), "=r"(r3) : "r"(addr))

#define MMA16816(c, a, b) \
    asm volatile("mma.sync.aligned.m16n8k16.row.col.f32.f16.f16.f32 " \
                 "{%0,%1,%2,%3}, {%4,%5,%6,%7}, {%8,%9}, {%0,%1,%2,%3};" \
                 : "+f"((c)[0]), "+f"((c)[1]), "+f"((c)[2]), "+f"((c)[3]) \
                 : "r"((a)[0]), "r"((a)[1]), "r"((a)[2]), "r"((a)[3]), \
                   "r"((b)[0]), "r"((b)[1]))

__device__ __forceinline__ uint32_t h2u(__half2 v) {
    uint32_t u; memcpy(&u, &v, 4); return u;
}

// ------------------------------------------------------------------
// Conversion kernels (as in the 371us configuration)
// ------------------------------------------------------------------
// fp32 -> fp16 cast (float4 loads)
__global__ __launch_bounds__(256) void convert_cast(
    const float* __restrict__ in, __half* __restrict__ outp)
{
    size_t i = ((size_t)blockIdx.x * 256 + threadIdx.x) * 4;
    float4 v = *(const float4*)(in + i);
    *(__half2*)(outp + i)     = __halves2half2(__float2half_rn(v.x), __float2half_rn(v.y));
    *(__half2*)(outp + i + 2) = __halves2half2(__float2half_rn(v.z), __float2half_rn(v.w));
}

// All four W[K,N] -> W^T [N,K] fp16, one launch; Wq scale folded in
__global__ __launch_bounds__(256) void convert_w_all(
    const float* __restrict__ Wq, const float* __restrict__ Wk,
    const float* __restrict__ Wv, const float* __restrict__ Wo)
{
    __shared__ float tile[32][33];
    int z = blockIdx.z;
    const float* W = (z == 0) ? Wq : (z == 1) ? Wk : (z == 2) ? Wv : Wo;
    float scale = (z == 0) ? 0.08838834764831845f : 1.0f;
    __half* t = g_wt + (size_t)z * DIM * DIM;

    int n0 = blockIdx.x * 32, k0 = blockIdx.y * 32;
    int tx = threadIdx.x, ty = threadIdx.y;   // (32, 8)
#pragma unroll
    for (int tt = 0; tt < 4; ++tt)
        tile[ty + 8 * tt][tx] = W[(size_t)(k0 + ty + 8 * tt) * DIM + n0 + tx] * scale;
    __syncthreads();
#pragma unroll
    for (int tt = 0; tt < 4; ++tt) {
        int r = ty + 8 * tt;
        t[(size_t)(n0 + r) * DIM + k0 + tx] = __float2half_rn(tile[tx][r]);
    }
}

// ------------------------------------------------------------------
// mma.sync fp16 GEMM (1-term): out = A @ B^T + bias
// CTA 128x128, KC=64, cp.async double buffer, ONE barrier per chunk,
// 2 CTAs/SM.
// ------------------------------------------------------------------
#define TMM 128
#define TNN 128
#define KC 64
#define NCHUNK (DIM / KC)
#define LSTRIDE 144
#define TILE_B (128 * LSTRIDE)      // 18432
#define OFF_A 0
#define OFF_B (1 * TILE_B)
#define STAGE_B (2 * TILE_B)        // 36864
#define GEMM_SMEM (2 * STAGE_B)     // 73728

__device__ __forceinline__ void load_chunk(
    uint32_t sbase, const __half* __restrict__ A, const __half* __restrict__ B,
    int row0, int col0, int k0, int tid)
{
    const int col16 = tid & 7;
    const int rb    = tid >> 3;
    const int kg    = k0 + col16 * 8;
#pragma unroll
    for (int t = 0; t < 4; ++t) {
        int r = rb + t * 32;
        uint32_t so = r * LSTRIDE + col16 * 16;
        CP_ASYNC16(sbase + OFF_A + so, A + (size_t)(row0 + r) * DIM + kg);
        CP_ASYNC16(sbase + OFF_B + so, B + (size_t)(col0 + r) * DIM + kg);
    }
}

// mode 0: fp32 [S][DIM]; mode 2: fp16 scatter [H][S][DK]
__device__ __forceinline__ void gemm_tc_body(
    const __half* __restrict__ A, const __half* __restrict__ B,
    const float* __restrict__ bias, float bscale,
    float* __restrict__ outp, __half* __restrict__ ohi, int mode)
{
    extern __shared__ char smg[];
    const int tid  = threadIdx.x;
    const int wid  = tid >> 5;
    const int lane = tid & 31;
    const int row0 = blockIdx.y * TMM;
    const int col0 = blockIdx.x * TNN;
    const int wm   = (wid & 3) * 32;
    const int wn   = (wid >> 2) * 64;
    const uint32_t sb = smem_u32(smg);

    float c[2][8][4];
#pragma unroll
    for (int mt = 0; mt < 2; ++mt)
#pragma unroll
        for (int nt = 0; nt < 8; ++nt)
#pragma unroll
            for (int j = 0; j < 4; ++j) c[mt][nt][j] = 0.0f;

    const uint32_t a_off = (wm + (lane & 15)) * LSTRIDE + (lane >> 4) * 16;
    const uint32_t b_row = wn + (lane & 7) + ((lane >> 4) & 1) * 8;
    const uint32_t b_off = b_row * LSTRIDE + ((lane >> 3) & 1) * 16;

    // prologue: stage 0
    load_chunk(sb, A, B, row0, col0, 0, tid);
    CP_COMMIT();

    for (int ch = 0; ch < NCHUNK; ++ch) {
        // Wait for chunk ch's data (only one group outstanding at this point),
        // then one barrier per chunk. Next-stage loads are issued AFTER the
        // barrier, so they cannot collide with the stage all warps just
        // finished reading (disjoint stage this iteration; reuse only after
        // the next barrier).
        CP_WAIT0();
        __syncthreads();
        if (ch + 1 < NCHUNK) {
            load_chunk(sb + ((ch + 1) & 1) * STAGE_B, A, B, row0, col0,
                       (ch + 1) * KC, tid);
            CP_COMMIT();
        }

        const uint32_t stage = sb + (ch & 1) * STAGE_B;
#pragma unroll
        for (int ks = 0; ks < 4; ++ks) {
            const uint32_t kb = ks * 32;
            uint32_t a[2][4];
#pragma unroll
            for (int mt = 0; mt < 2; ++mt) {
                uint32_t ad = stage + (uint32_t)(mt * 16 * LSTRIDE) + a_off + kb;
                LDSM_X4(a[mt][0], a[mt][1], a[mt][2], a[mt][3], ad + OFF_A);
            }
            uint32_t b[8][2];
#pragma unroll
            for (int q = 0; q < 4; ++q) {
                uint32_t bd = stage + (uint32_t)(q * 16 * LSTRIDE) + b_off + kb;
                LDSM_X4(b[2 * q][0], b[2 * q][1], b[2 * q + 1][0], b[2 * q + 1][1],
                        bd + OFF_B);
            }
#pragma unroll
            for (int mt = 0; mt < 2; ++mt)
#pragma unroll
                for (int nt = 0; nt < 8; ++nt)
                    MMA16816(c[mt][nt], a[mt], b[nt]);
        }
        // no trailing barrier: next iteration's top barrier provides the sync
    }

#pragma unroll
    for (int mt = 0; mt < 2; ++mt) {
#pragma unroll
        for (int nt = 0; nt < 8; ++nt) {
            int cg = col0 + wn + nt * 8 + (lane & 3) * 2;
            float b0 = bias[cg] * bscale;
            float b1 = bias[cg + 1] * bscale;
            int r0 = row0 + wm + mt * 16 + (lane >> 2);
#pragma unroll
            for (int hh = 0; hh < 2; ++hh) {
                int r = r0 + hh * 8;
                float v0 = c[mt][nt][2 * hh + 0] + b0;
                float v1 = c[mt][nt][2 * hh + 1] + b1;
                if (mode == 0) {
                    float* ob = outp + (size_t)r * DIM + cg;
                    ob[0] = v0; ob[1] = v1;
                } else {
                    int hd = cg >> 7, d0 = cg & 127;
                    size_t base = ((size_t)hd * SEQ + r) * DK + d0;
                    *(__half2*)(ohi + base) =
                        __halves2half2(__float2half_rn(v0), __float2half_rn(v1));
                }
            }
        }
    }
}

__global__ __launch_bounds__(256, 2) void qkv_tc(
    const float* __restrict__ bq, const float* __restrict__ bk, const float* __restrict__ bvv)
{
    int z = blockIdx.z;
    const __half* W = g_wt + (size_t)z * DIM * DIM;
    const float* bias = (z == 0) ? bq : (z == 1) ? bk : bvv;
    __half* outp = (z == 0) ? g_q : (z == 1) ? g_k : g_v;
    float bscale = (z == 0) ? 0.08838834764831845f : 1.0f;
    gemm_tc_body(g_a, W, bias, bscale, nullptr, outp, 2);
}

__global__ __launch_bounds__(256, 2) void out_tc(const float* __restrict__ bo, float* __restrict__ out)
{
    gemm_tc_body(g_a, g_wt + (size_t)3 * DIM * DIM, bo, 1.0f, out, nullptr, 0);
}

// ------------------------------------------------------------------
// mma.sync fp16 causal flash attention — cross-tile software pipeline.
// Q, K, V, P all fp16 (1-term QK, 1-term PV). Q fragments register-
// resident across tiles. Per tile jt: QK_jt, then deferred PV_{jt-1},
// then softmax_jt + pack. 4-stage KV ring, one __syncthreads per tile.
// CTA: 128 q-rows x 1 head, 256 threads (8 warps x 16 rows).
// ------------------------------------------------------------------
#define QT 128
#define KT 64
#define QSTR 272                      // 256B payload + 16B pad
#define QB 0                          // Q: 128 rows x QSTR = 34816
#define QB_TOT (128 * QSTR)           // 34816
#define SK 0                          // K: 64 rows x QSTR = 17408
#define SV (64 * QSTR)                // V: 64 rows x QSTR = 17408
#define STAGE_SZ (2 * 64 * QSTR)      // 34816 per KV stage
#define NSTAGE 4
#define ATTN_SMEM (QB_TOT + NSTAGE * STAGE_SZ)   // 174080

__device__ __forceinline__ void attn_load_kv(uint32_t st, int h, int kv0, int tid)
{
    const __half* kh = g_k + ((size_t)h * SEQ + kv0) * DK;
    const __half* vh = g_v + ((size_t)h * SEQ + kv0) * DK;
    int r = tid >> 2;                 // 0..63
#pragma unroll
    for (int i = 0; i < 4; ++i) {
        int u = (tid & 3) * 4 + i;
        CP_ASYNC16(st + SK + r * QSTR + u * 16, kh + (size_t)r * DK + u * 8);
        CP_ASYNC16(st + SV + r * QSTR + u * 16, vh + (size_t)r * DK + u * 8);
    }
}

__global__ __launch_bounds__(256, 1) void attn_mma()
{
    extern __shared__ char sma[];
    const uint32_t sb = smem_u32(sma);
    const int tid  = threadIdx.x;
    const int wid  = tid >> 5;
    const int lane = tid & 31;
    const int h    = blockIdx.y;
    const int qi   = 15 - blockIdx.x;      // heavy tiles first
    const int q0   = qi * QT;
    const int ntiles = 2 * (qi + 1);

    // prologue: Q tile + stage 0 KV
    {
        const __half* qh = g_q + ((size_t)h * SEQ + q0) * DK;
        int r = tid >> 1;
#pragma unroll
        for (int i = 0; i < 8; ++i) {
            int u = (tid & 1) * 8 + i;
            CP_ASYNC16(sb + QB + r * QSTR + u * 16, qh + (size_t)r * DK + u * 8);
        }
        attn_load_kv(sb + QB_TOT, h, 0, tid);
        CP_COMMIT();
    }

    // per-lane fragment address components
    const uint32_t a_off  = (wid * 16 + (lane & 15)) * QSTR + (lane >> 4) * 16;
    const uint32_t bk_off = ((lane & 7) + ((lane >> 4) & 1) * 8) * QSTR + ((lane >> 3) & 1) * 16;
    // V via ldmatrix.trans: tiles (k0-7,d0)(k8-15,d0)(k0-7,d1)(k8-15,d1)
    const uint32_t bv_off = ((lane & 7) + ((lane >> 3) & 1) * 8) * QSTR + ((lane >> 4) & 1) * 16;

    const int row0_abs = q0 + wid * 16 + (lane >> 2);
    const int rowmax   = q0 + wid * 16 + 15;

    float o[16][4];
#pragma unroll
    for (int nt = 0; nt < 16; ++nt)
#pragma unroll
        for (int j = 0; j < 4; ++j) o[nt][j] = 0.0f;
    float m0 = -1e4f, m1 = -1e4f, l0 = 0.0f, l1 = 0.0f;

    // register-resident Q fragments (loaded once at jt==0)
    uint32_t qa[8][4];
    // deferred-PV state (P fp16, 1-term)
    uint32_t aph[4][4];
    uint32_t prev_st = 0;
    int have_prev = 0;

    for (int jt = 0; jt < ntiles; ++jt) {
        if (jt + 1 < ntiles) {
            attn_load_kv(sb + QB_TOT + ((jt + 1) & (NSTAGE - 1)) * STAGE_SZ,
                         h, (jt + 1) * KT, tid);
            CP_COMMIT();
            CP_WAIT1();
        } else {
            CP_WAIT0();
        }
        __syncthreads();   // single barrier per tile (4-stage ring)

        if (jt == 0) {
            // Q smem is final now; hoist all Q fragments into registers
#pragma unroll
            for (int ks = 0; ks < 8; ++ks)
                LDSM_X4(qa[ks][0], qa[ks][1], qa[ks][2], qa[ks][3],
                        sb + QB + a_off + ks * 32);
        }

        const int kv0 = jt * KT;
        const int active = (kv0 <= rowmax);
        const uint32_t st = sb + QB_TOT + (jt & (NSTAGE - 1)) * STAGE_SZ;

        // ---- issue QK_jt (Q from registers) ----
        float s[8][4];
        if (active) {
#pragma unroll
            for (int nt = 0; nt < 8; ++nt)
#pragma unroll
                for (int j = 0; j < 4; ++j) s[nt][j] = 0.0f;
#pragma unroll
            for (int ks = 0; ks < 8; ++ks) {
                uint32_t bh[8][2];
#pragma unroll
                for (int q = 0; q < 4; ++q) {
                    uint32_t ba = st + SK + bk_off + q * (16 * QSTR) + ks * 32;
                    LDSM_X4(bh[2 * q][0], bh[2 * q][1], bh[2 * q + 1][0], bh[2 * q + 1][1], ba);
                }
#pragma unroll
                for (int nt = 0; nt < 8; ++nt) MMA16816(s[nt], qa[ks], bh[nt]);
            }
        }

        // ---- deferred PV_{jt-1}: overlaps the QK->softmax dependency ----
        if (have_prev) {
#pragma unroll
            for (int kp = 0; kp < 4; ++kp) {
#pragma unroll
                for (int p = 0; p < 8; ++p) {
                    uint32_t r0, r1, r2, r3;
                    LDSM_X4_T(r0, r1, r2, r3,
                              prev_st + SV + bv_off + kp * (16 * QSTR) + p * 32);
                    uint32_t b01[2] = {r0, r1};
                    uint32_t b23[2] = {r2, r3};
                    MMA16816(o[2 * p + 0], aph[kp], b01);
                    MMA16816(o[2 * p + 1], aph[kp], b23);
                }
            }
            have_prev = 0;
        }

        if (active) {
            // ---- causal mask ----
            if (kv0 + KT - 1 > q0 + wid * 16) {
#pragma unroll
                for (int nt = 0; nt < 8; ++nt) {
                    int cb = kv0 + nt * 8 + (lane & 3) * 2;
#pragma unroll
                    for (int j = 0; j < 4; ++j) {
                        int col = cb + (j & 1);
                        int row = row0_abs + (j >> 1) * 8;
                        if (col > row) s[nt][j] = -1e30f;
                    }
                }
            }

            // ---- online softmax ----
            float tm0 = -1e30f, tm1 = -1e30f;
#pragma unroll
            for (int nt = 0; nt < 8; ++nt) {
                tm0 = fmaxf(tm0, fmaxf(s[nt][0], s[nt][1]));
                tm1 = fmaxf(tm1, fmaxf(s[nt][2], s[nt][3]));
            }
            tm0 = fmaxf(tm0, __shfl_xor_sync(0xffffffffu, tm0, 1));
            tm0 = fmaxf(tm0, __shfl_xor_sync(0xffffffffu, tm0, 2));
            tm1 = fmaxf(tm1, __shfl_xor_sync(0xffffffffu, tm1, 1));
            tm1 = fmaxf(tm1, __shfl_xor_sync(0xffffffffu, tm1, 2));
            float mn0 = fmaxf(fmaxf(m0, tm0), -1e4f);
            float mn1 = fmaxf(fmaxf(m1, tm1), -1e4f);
            float al0 = __expf(m0 - mn0), al1 = __expf(m1 - mn1);
            m0 = mn0; m1 = mn1;
            float ls0 = 0.0f, ls1 = 0.0f;
#pragma unroll
            for (int nt = 0; nt < 8; ++nt) {
                s[nt][0] = __expf(s[nt][0] - mn0);
                s[nt][1] = __expf(s[nt][1] - mn0);
                s[nt][2] = __expf(s[nt][2] - mn1);
                s[nt][3] = __expf(s[nt][3] - mn1);
                ls0 += s[nt][0] + s[nt][1];
                ls1 += s[nt][2] + s[nt][3];
            }
            l0 = l0 * al0 + ls0;
            l1 = l1 * al1 + ls1;
#pragma unroll
            for (int nt = 0; nt < 16; ++nt) {
                o[nt][0] *= al0; o[nt][1] *= al0;
                o[nt][2] *= al1; o[nt][3] *= al1;
            }

            // ---- pack P_jt into PV A-frags (fp16, 1-term), defer the MMAs ----
#pragma unroll
            for (int pr = 0; pr < 4; ++pr) {
#pragma unroll
                for (int half = 0; half < 2; ++half) {
                    int nt = 2 * pr + half;
                    aph[pr][2 * half + 0] =
                        h2u(__halves2half2(__float2half_rn(s[nt][0]),
                                           __float2half_rn(s[nt][1])));
                    aph[pr][2 * half + 1] =
                        h2u(__halves2half2(__float2half_rn(s[nt][2]),
                                           __float2half_rn(s[nt][3])));
                }
            }
            prev_st = st;
            have_prev = 1;
        }
    }

    // ---- drain last deferred PV ----
    if (have_prev) {
#pragma unroll
        for (int kp = 0; kp < 4; ++kp) {
#pragma unroll
            for (int p = 0; p < 8; ++p) {
                uint32_t r0, r1, r2, r3;
                LDSM_X4_T(r0, r1, r2, r3,
                          prev_st + SV + bv_off + kp * (16 * QSTR) + p * 32);
                uint32_t b01[2] = {r0, r1};
                uint32_t b23[2] = {r2, r3};
                MMA16816(o[2 * p + 0], aph[kp], b01);
                MMA16816(o[2 * p + 1], aph[kp], b23);
            }
        }
    }

    // ---- epilogue: normalize, cast fp16, write att into A operand ----
    l0 += __shfl_xor_sync(0xffffffffu, l0, 1);
    l0 += __shfl_xor_sync(0xffffffffu, l0, 2);
    l1 += __shfl_xor_sync(0xffffffffu, l1, 1);
    l1 += __shfl_xor_sync(0xffffffffu, l1, 2);
    float inv0 = 1.0f / l0, inv1 = 1.0f / l1;

    const int r0 = row0_abs;
    const int r1 = row0_abs + 8;
#pragma unroll
    for (int nt = 0; nt < 16; ++nt) {
        int d = h * DK + nt * 8 + (lane & 3) * 2;
        *(__half2*)(g_a + (size_t)r0 * DIM + d) =
            __halves2half2(__float2half_rn(o[nt][0] * inv0),
                           __float2half_rn(o[nt][1] * inv0));
        *(__half2*)(g_a + (size_t)r1 * DIM + d) =
            __halves2half2(__float2half_rn(o[nt][2] * inv1),
                           __float2half_rn(o[nt][3] * inv1));
    }
}

// ------------------------------------------------------------------
// Launch
// ------------------------------------------------------------------
extern "C" void kernel_launch(void* const* d_in, const int* in_sizes, int n_in,
                              void* d_out, int out_size)
{
    const float* x  = (const float*)d_in[0];
    const float* Wq = (const float*)d_in[1];
    const float* bq = (const float*)d_in[2];
    const float* Wk = (const float*)d_in[3];
    const float* bk = (const float*)d_in[4];
    const float* Wv = (const float*)d_in[5];
    const float* bv = (const float*)d_in[6];
    const float* Wo = (const float*)d_in[7];
    const float* bo = (const float*)d_in[8];
    float* out = (float*)d_out;

    __half* a;
    cudaGetSymbolAddress((void**)&a, g_a);

    cudaFuncSetAttribute(qkv_tc, cudaFuncAttributeMaxDynamicSharedMemorySize, GEMM_SMEM);
    cudaFuncSetAttribute(out_tc, cudaFuncAttributeMaxDynamicSharedMemorySize, GEMM_SMEM);
    cudaFuncSetAttribute(attn_mma, cudaFuncAttributeMaxDynamicSharedMemorySize, ATTN_SMEM);

    dim3 tblk(32, 8);

    // 1) operand conversions (two launches, as in the 371us config)
    convert_cast<<<SEQ * DIM / 1024, 256>>>(x, a);
    convert_w_all<<<dim3(DIM / 32, DIM / 32, 4), tblk>>>(Wq, Wk, Wv, Wo);

    // 2) Q/K/V projections (all 1-term fp16)
    qkv_tc<<<dim3(DIM / TNN, SEQ / TMM, 3), 256, GEMM_SMEM>>>(bq, bk, bv);

    // 3) tensor-core causal flash attention (deferred-PV pipeline)
    attn_mma<<<dim3(SEQ / QT, NH), 256, ATTN_SMEM>>>();

    // 4) output projection (1-term)
    out_tc<<<dim3(DIM / TNN, SEQ / TMM), 256, GEMM_SMEM>>>(bo, out);
}

// round 15
// speedup vs baseline: 1.5556x; 1.0224x over previous
#include <cuda_runtime.h>
#include <cuda_fp16.h>
#include <cstdint>
#include <string.h>
#include <math.h>

// Problem constants
#define SEQ 2048
#define DIM 2048
#define NH  16
#define DK  128

// ------------------------------------------------------------------
// Scratch (device globals)
// ------------------------------------------------------------------
__device__ __half g_a[SEQ * DIM];             // A operand (x, then att), fp16
__device__ __half g_w[4u * DIM * DIM];        // W per matrix, RAW [K,N] layout, fp16
__device__ __half g_q[NH * SEQ * DK];         // Q fp16 (1/sqrt(dk) folded at epilogue)
__device__ __half g_k[NH * SEQ * DK];         // K fp16
__device__ __half g_v[NH * SEQ * DK];         // V fp16 (row-major, trans at ldmatrix)

// ------------------------------------------------------------------
// Baseline-PTX helpers (sm_80-level)
// ------------------------------------------------------------------
__device__ __forceinline__ uint32_t smem_u32(const void* p) {
    uint32_t a;
    asm("{ .reg .u64 t; cvta.to.shared.u64 t, %1; cvt.u32.u64 %0, t; }" : "=r"(a) : "l"(p));
    return a;
}

#define CP_ASYNC16(sm, gp) \
    asm volatile("cp.async.cg.shared.global [%0], [%1], 16;" :: "r"(sm), "l"(gp))
#define CP_COMMIT() asm volatile("cp.async.commit_group;" ::: "memory")
#define CP_WAIT1()  asm volatile("cp.async.wait_group 1;" ::: "memory")
#define CP_WAIT0()  asm volatile("cp.async.wait_group 0;" ::: "memory")

#define LDSM_X4(r0, r1, r2, r3, addr) \
    asm volatile("ldmatrix.sync.aligned.m8n8.x4.shared.b16 {%0,%1,%2,%3}, [%4];" \
                 : "=r"(r0), "=r"(r1), "=r"(r2), "=r"(r3) : "r"(addr))

#define LDSM_X4_T(r0, r1, r2, r3, addr) \
    asm volatile("ldmatrix.sync.aligned.m8n8.x4.trans.shared.b16 {%0,%1,%2,%3}, [%4];" \
                 : "=r"(r0), "=r"(r1), "=r"(r2), "=r"(r3) : "r"(addr))

#define MMA16816(c, a, b) \
    asm volatile("mma.sync.aligned.m16n8k16.row.col.f32.f16.f16.f32 " \
                 "{%0,%1,%2,%3}, {%4,%5,%6,%7}, {%8,%9}, {%0,%1,%2,%3};" \
                 : "+f"((c)[0]), "+f"((c)[1]), "+f"((c)[2]), "+f"((c)[3]) \
                 : "r"((a)[0]), "r"((a)[1]), "r"((a)[2]), "r"((a)[3]), \
                   "r"((b)[0]), "r"((b)[1]))

__device__ __forceinline__ uint32_t h2u(__half2 v) {
    uint32_t u; memcpy(&u, &v, 4); return u;
}

// ------------------------------------------------------------------
// Conversion kernels — pure streaming casts (no transpose)
// ------------------------------------------------------------------
// x fp32 -> fp16
__global__ __launch_bounds__(256) void convert_cast(
    const float* __restrict__ in, __half* __restrict__ outp)
{
    size_t i = ((size_t)blockIdx.x * 256 + threadIdx.x) * 4;
    float4 v = *(const float4*)(in + i);
    *(__half2*)(outp + i)     = __halves2half2(__float2half_rn(v.x), __float2half_rn(v.y));
    *(__half2*)(outp + i + 2) = __halves2half2(__float2half_rn(v.z), __float2half_rn(v.w));
}

// All four W fp32 -> fp16, RAW layout (no transpose, no scale)
__global__ __launch_bounds__(256) void convert_w_cast(
    const float* __restrict__ Wq, const float* __restrict__ Wk,
    const float* __restrict__ Wv, const float* __restrict__ Wo)
{
    int z = blockIdx.y;
    const float* W = (z == 0) ? Wq : (z == 1) ? Wk : (z == 2) ? Wv : Wo;
    __half* outp = g_w + (size_t)z * DIM * DIM;
    size_t i = ((size_t)blockIdx.x * 256 + threadIdx.x) * 4;
    float4 v = *(const float4*)(W + i);
    *(__half2*)(outp + i)     = __halves2half2(__float2half_rn(v.x), __float2half_rn(v.y));
    *(__half2*)(outp + i + 2) = __halves2half2(__float2half_rn(v.z), __float2half_rn(v.w));
}

// ------------------------------------------------------------------
// mma.sync fp16 GEMM (1-term): out = A @ W + bias, W RAW [K,N].
// B fragments via ldmatrix.trans on raw W tiles (same pattern as the
// attention V path). CTA 128x128, KC=64, cp.async double buffer,
// one barrier per chunk, 2 CTAs/SM.
// ------------------------------------------------------------------
#define TMM 128
#define TNN 128
#define KC 64
#define NCHUNK (DIM / KC)
#define ASTR 144                     // A row stride (128B payload + pad)
#define BSTR 272                     // B row stride (256B payload + pad)
#define A_TILE (128 * ASTR)          // 18432
#define B_TILE (64 * BSTR)           // 17408
#define OFF_A 0
#define OFF_B A_TILE
#define STAGE_B (A_TILE + B_TILE)    // 35840
#define GEMM_SMEM (2 * STAGE_B)      // 71680

__device__ __forceinline__ void load_chunk(
    uint32_t sbase, const __half* __restrict__ A, const __half* __restrict__ W,
    int row0, int col0, int k0, int tid)
{
    // A: 128 rows x 128B (k-major)
    {
        const int col16 = tid & 7;
        const int rb    = tid >> 3;
        const int kg    = k0 + col16 * 8;
#pragma unroll
        for (int t = 0; t < 4; ++t) {
            int r = rb + t * 32;
            CP_ASYNC16(sbase + OFF_A + r * ASTR + col16 * 16,
                       A + (size_t)(row0 + r) * DIM + kg);
        }
    }
    // B: 64 k-rows x 256B (raw W[K,N] slice)
    {
#pragma unroll
        for (int t = 0; t < 4; ++t) {
            int u = tid + t * 256;
            int r = u >> 4, c16 = u & 15;
            CP_ASYNC16(sbase + OFF_B + r * BSTR + c16 * 16,
                       W + (size_t)(k0 + r) * DIM + col0 + c16 * 8);
        }
    }
}

// mode 0: fp32 [S][DIM]; mode 2: fp16 scatter [H][S][DK]
// Output scale (bscale) applied to BOTH matmul result and bias.
__device__ __forceinline__ void gemm_tc_body(
    const __half* __restrict__ A, const __half* __restrict__ W,
    const float* __restrict__ bias, float bscale,
    float* __restrict__ outp, __half* __restrict__ ohi, int mode)
{
    extern __shared__ char smg[];
    const int tid  = threadIdx.x;
    const int wid  = tid >> 5;
    const int lane = tid & 31;
    const int row0 = blockIdx.y * TMM;
    const int col0 = blockIdx.x * TNN;
    const int wm   = (wid & 3) * 32;
    const int wn   = (wid >> 2) * 64;
    const uint32_t sb = smem_u32(smg);

    float c[2][8][4];
#pragma unroll
    for (int mt = 0; mt < 2; ++mt)
#pragma unroll
        for (int nt = 0; nt < 8; ++nt)
#pragma unroll
            for (int j = 0; j < 4; ++j) c[mt][nt][j] = 0.0f;

    const uint32_t a_off = (wm + (lane & 15)) * ASTR + (lane >> 4) * 16;
    // B (trans): 16 k-rows per x4, lane mapping identical to attention's V path
    const uint32_t b_off = ((lane & 7) + ((lane >> 3) & 1) * 8) * BSTR
                         + ((lane >> 4) & 1) * 16 + wn * 2;

    load_chunk(sb, A, W, row0, col0, 0, tid);
    CP_COMMIT();

    for (int ch = 0; ch < NCHUNK; ++ch) {
        CP_WAIT0();
        __syncthreads();
        if (ch + 1 < NCHUNK) {
            load_chunk(sb + ((ch + 1) & 1) * STAGE_B, A, W, row0, col0,
                       (ch + 1) * KC, tid);
            CP_COMMIT();
        }

        const uint32_t stage = sb + (ch & 1) * STAGE_B;
#pragma unroll
        for (int ks = 0; ks < 4; ++ks) {
            uint32_t a[2][4];
#pragma unroll
            for (int mt = 0; mt < 2; ++mt) {
                uint32_t ad = stage + (uint32_t)(mt * 16 * ASTR) + a_off + ks * 32;
                LDSM_X4(a[mt][0], a[mt][1], a[mt][2], a[mt][3], ad + OFF_A);
            }
            uint32_t b[8][2];
#pragma unroll
            for (int pp = 0; pp < 4; ++pp) {
                uint32_t bd = stage + OFF_B + b_off
                            + (uint32_t)(ks * 16 * BSTR) + pp * 32;
                LDSM_X4_T(b[2 * pp][0], b[2 * pp][1],
                          b[2 * pp + 1][0], b[2 * pp + 1][1], bd);
            }
#pragma unroll
            for (int mt = 0; mt < 2; ++mt)
#pragma unroll
                for (int nt = 0; nt < 8; ++nt)
                    MMA16816(c[mt][nt], a[mt], b[nt]);
        }
        // next iteration's top barrier provides the sync
    }

#pragma unroll
    for (int mt = 0; mt < 2; ++mt) {
#pragma unroll
        for (int nt = 0; nt < 8; ++nt) {
            int cg = col0 + wn + nt * 8 + (lane & 3) * 2;
            float b0 = bias[cg] * bscale;
            float b1 = bias[cg + 1] * bscale;
            int r0 = row0 + wm + mt * 16 + (lane >> 2);
#pragma unroll
            for (int hh = 0; hh < 2; ++hh) {
                int r = r0 + hh * 8;
                float v0 = fmaf(c[mt][nt][2 * hh + 0], bscale, b0);
                float v1 = fmaf(c[mt][nt][2 * hh + 1], bscale, b1);
                if (mode == 0) {
                    float* ob = outp + (size_t)r * DIM + cg;
                    ob[0] = v0; ob[1] = v1;
                } else {
                    int hd = cg >> 7, d0 = cg & 127;
                    size_t base = ((size_t)hd * SEQ + r) * DK + d0;
                    *(__half2*)(ohi + base) =
                        __halves2half2(__float2half_rn(v0), __float2half_rn(v1));
                }
            }
        }
    }
}

__global__ __launch_bounds__(256, 2) void qkv_tc(
    const float* __restrict__ bq, const float* __restrict__ bk, const float* __restrict__ bvv)
{
    int z = blockIdx.z;
    const __half* W = g_w + (size_t)z * DIM * DIM;
    const float* bias = (z == 0) ? bq : (z == 1) ? bk : bvv;
    __half* outp = (z == 0) ? g_q : (z == 1) ? g_k : g_v;
    float bscale = (z == 0) ? 0.08838834764831845f : 1.0f;   // 1/sqrt(dk) on Q output
    gemm_tc_body(g_a, W, bias, bscale, nullptr, outp, 2);
}

__global__ __launch_bounds__(256, 2) void out_tc(const float* __restrict__ bo, float* __restrict__ out)
{
    gemm_tc_body(g_a, g_w + (size_t)3 * DIM * DIM, bo, 1.0f, out, nullptr, 0);
}

// ------------------------------------------------------------------
// mma.sync fp16 causal flash attention — cross-tile software pipeline.
// Q, K, V, P all fp16 (1-term QK, 1-term PV). Q fragments register-
// resident across tiles. Per tile jt: QK_jt, then deferred PV_{jt-1},
// then softmax_jt + pack. 4-stage KV ring, one __syncthreads per tile.
// CTA: 128 q-rows x 1 head, 256 threads (8 warps x 16 rows).
// (Unchanged from the 368.7us configuration.)
// ------------------------------------------------------------------
#define QT 128
#define KT 64
#define QSTR 272                      // 256B payload + 16B pad
#define QB 0                          // Q: 128 rows x QSTR = 34816
#define QB_TOT (128 * QSTR)           // 34816
#define SK 0                          // K: 64 rows x QSTR = 17408
#define SV (64 * QSTR)                // V: 64 rows x QSTR = 17408
#define STAGE_SZ (2 * 64 * QSTR)      // 34816 per KV stage
#define NSTAGE 4
#define ATTN_SMEM (QB_TOT + NSTAGE * STAGE_SZ)   // 174080

__device__ __forceinline__ void attn_load_kv(uint32_t st, int h, int kv0, int tid)
{
    const __half* kh = g_k + ((size_t)h * SEQ + kv0) * DK;
    const __half* vh = g_v + ((size_t)h * SEQ + kv0) * DK;
    int r = tid >> 2;                 // 0..63
#pragma unroll
    for (int i = 0; i < 4; ++i) {
        int u = (tid & 3) * 4 + i;
        CP_ASYNC16(st + SK + r * QSTR + u * 16, kh + (size_t)r * DK + u * 8);
        CP_ASYNC16(st + SV + r * QSTR + u * 16, vh + (size_t)r * DK + u * 8);
    }
}

__global__ __launch_bounds__(256, 1) void attn_mma()
{
    extern __shared__ char sma[];
    const uint32_t sb = smem_u32(sma);
    const int tid  = threadIdx.x;
    const int wid  = tid >> 5;
    const int lane = tid & 31;
    const int h    = blockIdx.y;
    const int qi   = 15 - blockIdx.x;      // heavy tiles first
    const int q0   = qi * QT;
    const int ntiles = 2 * (qi + 1);

    // prologue: Q tile + stage 0 KV
    {
        const __half* qh = g_q + ((size_t)h * SEQ + q0) * DK;
        int r = tid >> 1;
#pragma unroll
        for (int i = 0; i < 8; ++i) {
            int u = (tid & 1) * 8 + i;
            CP_ASYNC16(sb + QB + r * QSTR + u * 16, qh + (size_t)r * DK + u * 8);
        }
        attn_load_kv(sb + QB_TOT, h, 0, tid);
        CP_COMMIT();
    }

    // per-lane fragment address components
    const uint32_t a_off  = (wid * 16 + (lane & 15)) * QSTR + (lane >> 4) * 16;
    const uint32_t bk_off = ((lane & 7) + ((lane >> 4) & 1) * 8) * QSTR + ((lane >> 3) & 1) * 16;
    // V via ldmatrix.trans: tiles (k0-7,d0)(k8-15,d0)(k0-7,d1)(k8-15,d1)
    const uint32_t bv_off = ((lane & 7) + ((lane >> 3) & 1) * 8) * QSTR + ((lane >> 4) & 1) * 16;

    const int row0_abs = q0 + wid * 16 + (lane >> 2);
    const int rowmax   = q0 + wid * 16 + 15;

    float o[16][4];
#pragma unroll
    for (int nt = 0; nt < 16; ++nt)
#pragma unroll
        for (int j = 0; j < 4; ++j) o[nt][j] = 0.0f;
    float m0 = -1e4f, m1 = -1e4f, l0 = 0.0f, l1 = 0.0f;

    // register-resident Q fragments (loaded once at jt==0)
    uint32_t qa[8][4];
    // deferred-PV state (P fp16, 1-term)
    uint32_t aph[4][4];
    uint32_t prev_st = 0;
    int have_prev = 0;

    for (int jt = 0; jt < ntiles; ++jt) {
        if (jt + 1 < ntiles) {
            attn_load_kv(sb + QB_TOT + ((jt + 1) & (NSTAGE - 1)) * STAGE_SZ,
                         h, (jt + 1) * KT, tid);
            CP_COMMIT();
            CP_WAIT1();
        } else {
            CP_WAIT0();
        }
        __syncthreads();   // single barrier per tile (4-stage ring)

        if (jt == 0) {
            // Q smem is final now; hoist all Q fragments into registers
#pragma unroll
            for (int ks = 0; ks < 8; ++ks)
                LDSM_X4(qa[ks][0], qa[ks][1], qa[ks][2], qa[ks][3],
                        sb + QB + a_off + ks * 32);
        }

        const int kv0 = jt * KT;
        const int active = (kv0 <= rowmax);
        const uint32_t st = sb + QB_TOT + (jt & (NSTAGE - 1)) * STAGE_SZ;

        // ---- issue QK_jt (Q from registers) ----
        float s[8][4];
        if (active) {
#pragma unroll
            for (int nt = 0; nt < 8; ++nt)
#pragma unroll
                for (int j = 0; j < 4; ++j) s[nt][j] = 0.0f;
#pragma unroll
            for (int ks = 0; ks < 8; ++ks) {
                uint32_t bh[8][2];
#pragma unroll
                for (int q = 0; q < 4; ++q) {
                    uint32_t ba = st + SK + bk_off + q * (16 * QSTR) + ks * 32;
                    LDSM_X4(bh[2 * q][0], bh[2 * q][1], bh[2 * q + 1][0], bh[2 * q + 1][1], ba);
                }
#pragma unroll
                for (int nt = 0; nt < 8; ++nt) MMA16816(s[nt], qa[ks], bh[nt]);
            }
        }

        // ---- deferred PV_{jt-1}: overlaps the QK->softmax dependency ----
        if (have_prev) {
#pragma unroll
            for (int kp = 0; kp < 4; ++kp) {
#pragma unroll
                for (int p = 0; p < 8; ++p) {
                    uint32_t r0, r1, r2, r3;
                    LDSM_X4_T(r0, r1, r2, r3,
                              prev_st + SV + bv_off + kp * (16 * QSTR) + p * 32);
                    uint32_t b01[2] = {r0, r1};
                    uint32_t b23[2] = {r2, r3};
                    MMA16816(o[2 * p + 0], aph[kp], b01);
                    MMA16816(o[2 * p + 1], aph[kp], b23);
                }
            }
            have_prev = 0;
        }

        if (active) {
            // ---- causal mask ----
            if (kv0 + KT - 1 > q0 + wid * 16) {
#pragma unroll
                for (int nt = 0; nt < 8; ++nt) {
                    int cb = kv0 + nt * 8 + (lane & 3) * 2;
#pragma unroll
                    for (int j = 0; j < 4; ++j) {
                        int col = cb + (j & 1);
                        int row = row0_abs + (j >> 1) * 8;
                        if (col > row) s[nt][j] = -1e30f;
                    }
                }
            }

            // ---- online softmax ----
            float tm0 = -1e30f, tm1 = -1e30f;
#pragma unroll
            for (int nt = 0; nt < 8; ++nt) {
                tm0 = fmaxf(tm0, fmaxf(s[nt][0], s[nt][1]));
                tm1 = fmaxf(tm1, fmaxf(s[nt][2], s[nt][3]));
            }
            tm0 = fmaxf(tm0, __shfl_xor_sync(0xffffffffu, tm0, 1));
            tm0 = fmaxf(tm0, __shfl_xor_sync(0xffffffffu, tm0, 2));
            tm1 = fmaxf(tm1, __shfl_xor_sync(0xffffffffu, tm1, 1));
            tm1 = fmaxf(tm1, __shfl_xor_sync(0xffffffffu, tm1, 2));
            float mn0 = fmaxf(fmaxf(m0, tm0), -1e4f);
            float mn1 = fmaxf(fmaxf(m1, tm1), -1e4f);
            float al0 = __expf(m0 - mn0), al1 = __expf(m1 - mn1);
            m0 = mn0; m1 = mn1;
            float ls0 = 0.0f, ls1 = 0.0f;
#pragma unroll
            for (int nt = 0; nt < 8; ++nt) {
                s[nt][0] = __expf(s[nt][0] - mn0);
                s[nt][1] = __expf(s[nt][1] - mn0);
                s[nt][2] = __expf(s[nt][2] - mn1);
                s[nt][3] = __expf(s[nt][3] - mn1);
                ls0 += s[nt][0] + s[nt][1];
                ls1 += s[nt][2] + s[nt][3];
            }
            l0 = l0 * al0 + ls0;
            l1 = l1 * al1 + ls1;
#pragma unroll
            for (int nt = 0; nt < 16; ++nt) {
                o[nt][0] *= al0; o[nt][1] *= al0;
                o[nt][2] *= al1; o[nt][3] *= al1;
            }

            // ---- pack P_jt into PV A-frags (fp16, 1-term), defer the MMAs ----
#pragma unroll
            for (int pr = 0; pr < 4; ++pr) {
#pragma unroll
                for (int half = 0; half < 2; ++half) {
                    int nt = 2 * pr + half;
                    aph[pr][2 * half + 0] =
                        h2u(__halves2half2(__float2half_rn(s[nt][0]),
                                           __float2half_rn(s[nt][1])));
                    aph[pr][2 * half + 1] =
                        h2u(__halves2half2(__float2half_rn(s[nt][2]),
                                           __float2half_rn(s[nt][3])));
                }
            }
            prev_st = st;
            have_prev = 1;
        }
    }

    // ---- drain last deferred PV ----
    if (have_prev) {
#pragma unroll
        for (int kp = 0; kp < 4; ++kp) {
#pragma unroll
            for (int p = 0; p < 8; ++p) {
                uint32_t r0, r1, r2, r3;
                LDSM_X4_T(r0, r1, r2, r3,
                          prev_st + SV + bv_off + kp * (16 * QSTR) + p * 32);
                uint32_t b01[2] = {r0, r1};
                uint32_t b23[2] = {r2, r3};
                MMA16816(o[2 * p + 0], aph[kp], b01);
                MMA16816(o[2 * p + 1], aph[kp], b23);
            }
        }
    }

    // ---- epilogue: normalize, cast fp16, write att into A operand ----
    l0 += __shfl_xor_sync(0xffffffffu, l0, 1);
    l0 += __shfl_xor_sync(0xffffffffu, l0, 2);
    l1 += __shfl_xor_sync(0xffffffffu, l1, 1);
    l1 += __shfl_xor_sync(0xffffffffu, l1, 2);
    float inv0 = 1.0f / l0, inv1 = 1.0f / l1;

    const int r0 = row0_abs;
    const int r1 = row0_abs + 8;
#pragma unroll
    for (int nt = 0; nt < 16; ++nt) {
        int d = h * DK + nt * 8 + (lane & 3) * 2;
        *(__half2*)(g_a + (size_t)r0 * DIM + d) =
            __halves2half2(__float2half_rn(o[nt][0] * inv0),
                           __float2half_rn(o[nt][1] * inv0));
        *(__half2*)(g_a + (size_t)r1 * DIM + d) =
            __halves2half2(__float2half_rn(o[nt][2] * inv1),
                           __float2half_rn(o[nt][3] * inv1));
    }
}

// ------------------------------------------------------------------
// Launch
// ------------------------------------------------------------------
extern "C" void kernel_launch(void* const* d_in, const int* in_sizes, int n_in,
                              void* d_out, int out_size)
{
    const float* x  = (const float*)d_in[0];
    const float* Wq = (const float*)d_in[1];
    const float* bq = (const float*)d_in[2];
    const float* Wk = (const float*)d_in[3];
    const float* bk = (const float*)d_in[4];
    const float* Wv = (const float*)d_in[5];
    const float* bv = (const float*)d_in[6];
    const float* Wo = (const float*)d_in[7];
    const float* bo = (const float*)d_in[8];
    float* out = (float*)d_out;

    __half* a;
    cudaGetSymbolAddress((void**)&a, g_a);

    cudaFuncSetAttribute(qkv_tc, cudaFuncAttributeMaxDynamicSharedMemorySize, GEMM_SMEM);
    cudaFuncSetAttribute(out_tc, cudaFuncAttributeMaxDynamicSharedMemorySize, GEMM_SMEM);
    cudaFuncSetAttribute(attn_mma, cudaFuncAttributeMaxDynamicSharedMemorySize, ATTN_SMEM);

    // 1) operand conversions (pure streaming casts)
    convert_cast<<<SEQ * DIM / 1024, 256>>>(x, a);
    convert_w_cast<<<dim3(DIM * DIM / 1024, 4), 256>>>(Wq, Wk, Wv, Wo);

    // 2) Q/K/V projections (all 1-term fp16, raw-W B operand)
    qkv_tc<<<dim3(DIM / TNN, SEQ / TMM, 3), 256, GEMM_SMEM>>>(bq, bk, bv);

    // 3) tensor-core causal flash attention (deferred-PV pipeline)
    attn_mma<<<dim3(SEQ / QT, NH), 256, ATTN_SMEM>>>();

    // 4) output projection (1-term)
    out_tc<<<dim3(DIM / TNN, SEQ / TMM), 256, GEMM_SMEM>>>(bo, out);
}

// round 16
// speedup vs baseline: 1.7415x; 1.1195x over previous
#include <cuda_runtime.h>
#include <cuda_fp16.h>
#include <cstdint>
#include <string.h>
#include <math.h>

// Problem constants
#define SEQ 2048
#define DIM 2048
#define NH  16
#define DK  128

// ------------------------------------------------------------------
// Scratch (device globals)
// ------------------------------------------------------------------
__device__ __half g_a[SEQ * DIM];             // A operand (x, then att), fp16
__device__ __half g_w[4u * DIM * DIM];        // W per matrix, RAW [K,N] layout, fp16
__device__ __half g_q[NH * SEQ * DK];         // Q fp16 (1/sqrt(dk) folded at epilogue)
__device__ __half g_k[NH * SEQ * DK];         // K fp16
__device__ __half g_v[NH * SEQ * DK];         // V fp16 (row-major, trans at ldmatrix)

// ------------------------------------------------------------------
// Baseline-PTX helpers (sm_80-level)
// ------------------------------------------------------------------
__device__ __forceinline__ uint32_t smem_u32(const void* p) {
    uint32_t a;
    asm("{ .reg .u64 t; cvta.to.shared.u64 t, %1; cvt.u32.u64 %0, t; }" : "=r"(a) : "l"(p));
    return a;
}

#define CP_ASYNC16(sm, gp) \
    asm volatile("cp.async.cg.shared.global [%0], [%1], 16;" :: "r"(sm), "l"(gp))
#define CP_COMMIT() asm volatile("cp.async.commit_group;" ::: "memory")
#define CP_WAIT1()  asm volatile("cp.async.wait_group 1;" ::: "memory")
#define CP_WAIT0()  asm volatile("cp.async.wait_group 0;" ::: "memory")

#define LDSM_X4(r0, r1, r2, r3, addr) \
    asm volatile("ldmatrix.sync.aligned.m8n8.x4.shared.b16 {%0,%1,%2,%3}, [%4];" \
                 : "=r"(r0), "=r"(r1), "=r"(r2), "=r"(r3) : "r"(addr))

#define LDSM_X4_T(r0, r1, r2, r3, addr) \
    asm volatile("ldmatrix.sync.aligned.m8n8.x4.trans.shared.b16 {%0,%1,%2,%3}, [%4];" \
                 : "=r"(r0), "=r"(r1), "=r"(r2), "=r"(r3) : "r"(addr))

#define MMA16816(c, a, b) \
    asm volatile("mma.sync.aligned.m16n8k16.row.col.f32.f16.f16.f32 " \
                 "{%0,%1,%2,%3}, {%4,%5,%6,%7}, {%8,%9}, {%0,%1,%2,%3};" \
                 : "+f"((c)[0]), "+f"((c)[1]), "+f"((c)[2]), "+f"((c)[3]) \
                 : "r"((a)[0]), "r"((a)[1]), "r"((a)[2]), "r"((a)[3]), \
                   "r"((b)[0]), "r"((b)[1]))

__device__ __forceinline__ uint32_t h2u(__half2 v) {
    uint32_t u; memcpy(&u, &v, 4); return u;
}

// ------------------------------------------------------------------
// Conversion kernels — pure streaming casts (no transpose)
// ------------------------------------------------------------------
__global__ __launch_bounds__(256) void convert_cast(
    const float* __restrict__ in, __half* __restrict__ outp)
{
    size_t i = ((size_t)blockIdx.x * 256 + threadIdx.x) * 4;
    float4 v = *(const float4*)(in + i);
    *(__half2*)(outp + i)     = __halves2half2(__float2half_rn(v.x), __float2half_rn(v.y));
    *(__half2*)(outp + i + 2) = __halves2half2(__float2half_rn(v.z), __float2half_rn(v.w));
}

__global__ __launch_bounds__(256) void convert_w_cast(
    const float* __restrict__ Wq, const float* __restrict__ Wk,
    const float* __restrict__ Wv, const float* __restrict__ Wo)
{
    int z = blockIdx.y;
    const float* W = (z == 0) ? Wq : (z == 1) ? Wk : (z == 2) ? Wv : Wo;
    __half* outp = g_w + (size_t)z * DIM * DIM;
    size_t i = ((size_t)blockIdx.x * 256 + threadIdx.x) * 4;
    float4 v = *(const float4*)(W + i);
    *(__half2*)(outp + i)     = __halves2half2(__float2half_rn(v.x), __float2half_rn(v.y));
    *(__half2*)(outp + i + 2) = __halves2half2(__float2half_rn(v.z), __float2half_rn(v.w));
}

// ------------------------------------------------------------------
// mma.sync fp16 GEMM (1-term): out = A @ W + bias, W RAW [K,N].
// B fragments via ldmatrix.trans on raw W tiles. CTA 128x128, KC=64,
// cp.async double buffer, one barrier per chunk, 2 CTAs/SM.
// ------------------------------------------------------------------
#define TMM 128
#define TNN 128
#define KC 64
#define NCHUNK (DIM / KC)
#define ASTR 144                     // A row stride (128B payload + pad)
#define BSTR 272                     // B row stride (256B payload + pad)
#define A_TILE (128 * ASTR)          // 18432
#define B_TILE (64 * BSTR)           // 17408
#define OFF_A 0
#define OFF_B A_TILE
#define STAGE_B (A_TILE + B_TILE)    // 35840
#define GEMM_SMEM (2 * STAGE_B)      // 71680

__device__ __forceinline__ void load_chunk(
    uint32_t sbase, const __half* __restrict__ A, const __half* __restrict__ W,
    int row0, int col0, int k0, int tid)
{
    // A: 128 rows x 128B (k-major)
    {
        const int col16 = tid & 7;
        const int rb    = tid >> 3;
        const int kg    = k0 + col16 * 8;
#pragma unroll
        for (int t = 0; t < 4; ++t) {
            int r = rb + t * 32;
            CP_ASYNC16(sbase + OFF_A + r * ASTR + col16 * 16,
                       A + (size_t)(row0 + r) * DIM + kg);
        }
    }
    // B: 64 k-rows x 256B (raw W[K,N] slice)
    {
#pragma unroll
        for (int t = 0; t < 4; ++t) {
            int u = tid + t * 256;
            int r = u >> 4, c16 = u & 15;
            CP_ASYNC16(sbase + OFF_B + r * BSTR + c16 * 16,
                       W + (size_t)(k0 + r) * DIM + col0 + c16 * 8);
        }
    }
}

// mode 0: fp32 [S][DIM]; mode 2: fp16 scatter [H][S][DK]
__device__ __forceinline__ void gemm_tc_body(
    const __half* __restrict__ A, const __half* __restrict__ W,
    const float* __restrict__ bias, float bscale,
    float* __restrict__ outp, __half* __restrict__ ohi, int mode)
{
    extern __shared__ char smg[];
    const int tid  = threadIdx.x;
    const int wid  = tid >> 5;
    const int lane = tid & 31;
    const int row0 = blockIdx.y * TMM;
    const int col0 = blockIdx.x * TNN;
    const int wm   = (wid & 3) * 32;
    const int wn   = (wid >> 2) * 64;
    const uint32_t sb = smem_u32(smg);

    float c[2][8][4];
#pragma unroll
    for (int mt = 0; mt < 2; ++mt)
#pragma unroll
        for (int nt = 0; nt < 8; ++nt)
#pragma unroll
            for (int j = 0; j < 4; ++j) c[mt][nt][j] = 0.0f;

    const uint32_t a_off = (wm + (lane & 15)) * ASTR + (lane >> 4) * 16;
    const uint32_t b_off = ((lane & 7) + ((lane >> 3) & 1) * 8) * BSTR
                         + ((lane >> 4) & 1) * 16 + wn * 2;

    load_chunk(sb, A, W, row0, col0, 0, tid);
    CP_COMMIT();

    for (int ch = 0; ch < NCHUNK; ++ch) {
        CP_WAIT0();
        __syncthreads();
        if (ch + 1 < NCHUNK) {
            load_chunk(sb + ((ch + 1) & 1) * STAGE_B, A, W, row0, col0,
                       (ch + 1) * KC, tid);
            CP_COMMIT();
        }

        const uint32_t stage = sb + (ch & 1) * STAGE_B;
#pragma unroll
        for (int ks = 0; ks < 4; ++ks) {
            uint32_t a[2][4];
#pragma unroll
            for (int mt = 0; mt < 2; ++mt) {
                uint32_t ad = stage + (uint32_t)(mt * 16 * ASTR) + a_off + ks * 32;
                LDSM_X4(a[mt][0], a[mt][1], a[mt][2], a[mt][3], ad + OFF_A);
            }
            uint32_t b[8][2];
#pragma unroll
            for (int pp = 0; pp < 4; ++pp) {
                uint32_t bd = stage + OFF_B + b_off
                            + (uint32_t)(ks * 16 * BSTR) + pp * 32;
                LDSM_X4_T(b[2 * pp][0], b[2 * pp][1],
                          b[2 * pp + 1][0], b[2 * pp + 1][1], bd);
            }
#pragma unroll
            for (int mt = 0; mt < 2; ++mt)
#pragma unroll
                for (int nt = 0; nt < 8; ++nt)
                    MMA16816(c[mt][nt], a[mt], b[nt]);
        }
    }

#pragma unroll
    for (int mt = 0; mt < 2; ++mt) {
#pragma unroll
        for (int nt = 0; nt < 8; ++nt) {
            int cg = col0 + wn + nt * 8 + (lane & 3) * 2;
            float b0 = bias[cg] * bscale;
            float b1 = bias[cg + 1] * bscale;
            int r0 = row0 + wm + mt * 16 + (lane >> 2);
#pragma unroll
            for (int hh = 0; hh < 2; ++hh) {
                int r = r0 + hh * 8;
                float v0 = fmaf(c[mt][nt][2 * hh + 0], bscale, b0);
                float v1 = fmaf(c[mt][nt][2 * hh + 1], bscale, b1);
                if (mode == 0) {
                    float* ob = outp + (size_t)r * DIM + cg;
                    ob[0] = v0; ob[1] = v1;
                } else {
                    int hd = cg >> 7, d0 = cg & 127;
                    size_t base = ((size_t)hd * SEQ + r) * DK + d0;
                    *(__half2*)(ohi + base) =
                        __halves2half2(__float2half_rn(v0), __float2half_rn(v1));
                }
            }
        }
    }
}

__global__ __launch_bounds__(256, 2) void qkv_tc(
    const float* __restrict__ bq, const float* __restrict__ bk, const float* __restrict__ bvv)
{
    int z = blockIdx.z;
    const __half* W = g_w + (size_t)z * DIM * DIM;
    const float* bias = (z == 0) ? bq : (z == 1) ? bk : bvv;
    __half* outp = (z == 0) ? g_q : (z == 1) ? g_k : g_v;
    float bscale = (z == 0) ? 0.08838834764831845f : 1.0f;
    gemm_tc_body(g_a, W, bias, bscale, nullptr, outp, 2);
}

__global__ __launch_bounds__(256, 2) void out_tc(const float* __restrict__ bo, float* __restrict__ out)
{
    gemm_tc_body(g_a, g_w + (size_t)3 * DIM * DIM, bo, 1.0f, out, nullptr, 0);
}

// ------------------------------------------------------------------
// mma.sync fp16 causal flash attention — cross-tile software pipeline.
// GLOBAL heavy-first scheduling: grid(NH, SEQ/QT) with head on x
// (fastest), q-tile weight on y => the 148 heaviest CTAs dispatch
// first chip-wide; light CTAs backfill. Kernel body unchanged.
// ------------------------------------------------------------------
#define QT 128
#define KT 64
#define QSTR 272                      // 256B payload + 16B pad
#define QB 0                          // Q: 128 rows x QSTR = 34816
#define QB_TOT (128 * QSTR)           // 34816
#define SK 0                          // K: 64 rows x QSTR = 17408
#define SV (64 * QSTR)                // V: 64 rows x QSTR = 17408
#define STAGE_SZ (2 * 64 * QSTR)      // 34816 per KV stage
#define NSTAGE 4
#define ATTN_SMEM (QB_TOT + NSTAGE * STAGE_SZ)   // 174080

__device__ __forceinline__ void attn_load_kv(uint32_t st, int h, int kv0, int tid)
{
    const __half* kh = g_k + ((size_t)h * SEQ + kv0) * DK;
    const __half* vh = g_v + ((size_t)h * SEQ + kv0) * DK;
    int r = tid >> 2;                 // 0..63
#pragma unroll
    for (int i = 0; i < 4; ++i) {
        int u = (tid & 3) * 4 + i;
        CP_ASYNC16(st + SK + r * QSTR + u * 16, kh + (size_t)r * DK + u * 8);
        CP_ASYNC16(st + SV + r * QSTR + u * 16, vh + (size_t)r * DK + u * 8);
    }
}

__global__ __launch_bounds__(256, 1) void attn_mma()
{
    extern __shared__ char sma[];
    const uint32_t sb = smem_u32(sma);
    const int tid  = threadIdx.x;
    const int wid  = tid >> 5;
    const int lane = tid & 31;
    const int h    = blockIdx.x;           // head on FAST axis
    const int qi   = 15 - blockIdx.y;      // heavy q-tiles dispatch first globally
    const int q0   = qi * QT;
    const int ntiles = 2 * (qi + 1);

    // prologue: Q tile + stage 0 KV
    {
        const __half* qh = g_q + ((size_t)h * SEQ + q0) * DK;
        int r = tid >> 1;
#pragma unroll
        for (int i = 0; i < 8; ++i) {
            int u = (tid & 1) * 8 + i;
            CP_ASYNC16(sb + QB + r * QSTR + u * 16, qh + (size_t)r * DK + u * 8);
        }
        attn_load_kv(sb + QB_TOT, h, 0, tid);
        CP_COMMIT();
    }

    // per-lane fragment address components
    const uint32_t a_off  = (wid * 16 + (lane & 15)) * QSTR + (lane >> 4) * 16;
    const uint32_t bk_off = ((lane & 7) + ((lane >> 4) & 1) * 8) * QSTR + ((lane >> 3) & 1) * 16;
    const uint32_t bv_off = ((lane & 7) + ((lane >> 3) & 1) * 8) * QSTR + ((lane >> 4) & 1) * 16;

    const int row0_abs = q0 + wid * 16 + (lane >> 2);
    const int rowmax   = q0 + wid * 16 + 15;

    float o[16][4];
#pragma unroll
    for (int nt = 0; nt < 16; ++nt)
#pragma unroll
        for (int j = 0; j < 4; ++j) o[nt][j] = 0.0f;
    float m0 = -1e4f, m1 = -1e4f, l0 = 0.0f, l1 = 0.0f;

    uint32_t qa[8][4];
    uint32_t aph[4][4];
    uint32_t prev_st = 0;
    int have_prev = 0;

    for (int jt = 0; jt < ntiles; ++jt) {
        if (jt + 1 < ntiles) {
            attn_load_kv(sb + QB_TOT + ((jt + 1) & (NSTAGE - 1)) * STAGE_SZ,
                         h, (jt + 1) * KT, tid);
            CP_COMMIT();
            CP_WAIT1();
        } else {
            CP_WAIT0();
        }
        __syncthreads();   // single barrier per tile (4-stage ring)

        if (jt == 0) {
#pragma unroll
            for (int ks = 0; ks < 8; ++ks)
                LDSM_X4(qa[ks][0], qa[ks][1], qa[ks][2], qa[ks][3],
                        sb + QB + a_off + ks * 32);
        }

        const int kv0 = jt * KT;
        const int active = (kv0 <= rowmax);
        const uint32_t st = sb + QB_TOT + (jt & (NSTAGE - 1)) * STAGE_SZ;

        // ---- issue QK_jt (Q from registers) ----
        float s[8][4];
        if (active) {
#pragma unroll
            for (int nt = 0; nt < 8; ++nt)
#pragma unroll
                for (int j = 0; j < 4; ++j) s[nt][j] = 0.0f;
#pragma unroll
            for (int ks = 0; ks < 8; ++ks) {
                uint32_t bh[8][2];
#pragma unroll
                for (int q = 0; q < 4; ++q) {
                    uint32_t ba = st + SK + bk_off + q * (16 * QSTR) + ks * 32;
                    LDSM_X4(bh[2 * q][0], bh[2 * q][1], bh[2 * q + 1][0], bh[2 * q + 1][1], ba);
                }
#pragma unroll
                for (int nt = 0; nt < 8; ++nt) MMA16816(s[nt], qa[ks], bh[nt]);
            }
        }

        // ---- deferred PV_{jt-1}: overlaps the QK->softmax dependency ----
        if (have_prev) {
#pragma unroll
            for (int kp = 0; kp < 4; ++kp) {
#pragma unroll
                for (int p = 0; p < 8; ++p) {
                    uint32_t r0, r1, r2, r3;
                    LDSM_X4_T(r0, r1, r2, r3,
                              prev_st + SV + bv_off + kp * (16 * QSTR) + p * 32);
                    uint32_t b01[2] = {r0, r1};
                    uint32_t b23[2] = {r2, r3};
                    MMA16816(o[2 * p + 0], aph[kp], b01);
                    MMA16816(o[2 * p + 1], aph[kp], b23);
                }
            }
            have_prev = 0;
        }

        if (active) {
            // ---- causal mask ----
            if (kv0 + KT - 1 > q0 + wid * 16) {
#pragma unroll
                for (int nt = 0; nt < 8; ++nt) {
                    int cb = kv0 + nt * 8 + (lane & 3) * 2;
#pragma unroll
                    for (int j = 0; j < 4; ++j) {
                        int col = cb + (j & 1);
                        int row = row0_abs + (j >> 1) * 8;
                        if (col > row) s[nt][j] = -1e30f;
                    }
                }
            }

            // ---- online softmax ----
            float tm0 = -1e30f, tm1 = -1e30f;
#pragma unroll
            for (int nt = 0; nt < 8; ++nt) {
                tm0 = fmaxf(tm0, fmaxf(s[nt][0], s[nt][1]));
                tm1 = fmaxf(tm1, fmaxf(s[nt][2], s[nt][3]));
            }
            tm0 = fmaxf(tm0, __shfl_xor_sync(0xffffffffu, tm0, 1));
            tm0 = fmaxf(tm0, __shfl_xor_sync(0xffffffffu, tm0, 2));
            tm1 = fmaxf(tm1, __shfl_xor_sync(0xffffffffu, tm1, 1));
            tm1 = fmaxf(tm1, __shfl_xor_sync(0xffffffffu, tm1, 2));
            float mn0 = fmaxf(fmaxf(m0, tm0), -1e4f);
            float mn1 = fmaxf(fmaxf(m1, tm1), -1e4f);
            float al0 = __expf(m0 - mn0), al1 = __expf(m1 - mn1);
            m0 = mn0; m1 = mn1;
            float ls0 = 0.0f, ls1 = 0.0f;
#pragma unroll
            for (int nt = 0; nt < 8; ++nt) {
                s[nt][0] = __expf(s[nt][0] - mn0);
                s[nt][1] = __expf(s[nt][1] - mn0);
                s[nt][2] = __expf(s[nt][2] - mn1);
                s[nt][3] = __expf(s[nt][3] - mn1);
                ls0 += s[nt][0] + s[nt][1];
                ls1 += s[nt][2] + s[nt][3];
            }
            l0 = l0 * al0 + ls0;
            l1 = l1 * al1 + ls1;
#pragma unroll
            for (int nt = 0; nt < 16; ++nt) {
                o[nt][0] *= al0; o[nt][1] *= al0;
                o[nt][2] *= al1; o[nt][3] *= al1;
            }

            // ---- pack P_jt into PV A-frags (fp16, 1-term), defer the MMAs ----
#pragma unroll
            for (int pr = 0; pr < 4; ++pr) {
#pragma unroll
                for (int half = 0; half < 2; ++half) {
                    int nt = 2 * pr + half;
                    aph[pr][2 * half + 0] =
                        h2u(__halves2half2(__float2half_rn(s[nt][0]),
                                           __float2half_rn(s[nt][1])));
                    aph[pr][2 * half + 1] =
                        h2u(__halves2half2(__float2half_rn(s[nt][2]),
                                           __float2half_rn(s[nt][3])));
                }
            }
            prev_st = st;
            have_prev = 1;
        }
    }

    // ---- drain last deferred PV ----
    if (have_prev) {
#pragma unroll
        for (int kp = 0; kp < 4; ++kp) {
#pragma unroll
            for (int p = 0; p < 8; ++p) {
                uint32_t r0, r1, r2, r3;
                LDSM_X4_T(r0, r1, r2, r3,
                          prev_st + SV + bv_off + kp * (16 * QSTR) + p * 32);
                uint32_t b01[2] = {r0, r1};
                uint32_t b23[2] = {r2, r3};
                MMA16816(o[2 * p + 0], aph[kp], b01);
                MMA16816(o[2 * p + 1], aph[kp], b23);
            }
        }
    }

    // ---- epilogue: normalize, cast fp16, write att into A operand ----
    l0 += __shfl_xor_sync(0xffffffffu, l0, 1);
    l0 += __shfl_xor_sync(0xffffffffu, l0, 2);
    l1 += __shfl_xor_sync(0xffffffffu, l1, 1);
    l1 += __shfl_xor_sync(0xffffffffu, l1, 2);
    float inv0 = 1.0f / l0, inv1 = 1.0f / l1;

    const int r0 = row0_abs;
    const int r1 = row0_abs + 8;
#pragma unroll
    for (int nt = 0; nt < 16; ++nt) {
        int d = h * DK + nt * 8 + (lane & 3) * 2;
        *(__half2*)(g_a + (size_t)r0 * DIM + d) =
            __halves2half2(__float2half_rn(o[nt][0] * inv0),
                           __float2half_rn(o[nt][1] * inv0));
        *(__half2*)(g_a + (size_t)r1 * DIM + d) =
            __halves2half2(__float2half_rn(o[nt][2] * inv1),
                           __float2half_rn(o[nt][3] * inv1));
    }
}

// ------------------------------------------------------------------
// Launch
// ------------------------------------------------------------------
extern "C" void kernel_launch(void* const* d_in, const int* in_sizes, int n_in,
                              void* d_out, int out_size)
{
    const float* x  = (const float*)d_in[0];
    const float* Wq = (const float*)d_in[1];
    const float* bq = (const float*)d_in[2];
    const float* Wk = (const float*)d_in[3];
    const float* bk = (const float*)d_in[4];
    const float* Wv = (const float*)d_in[5];
    const float* bv = (const float*)d_in[6];
    const float* Wo = (const float*)d_in[7];
    const float* bo = (const float*)d_in[8];
    float* out = (float*)d_out;

    __half* a;
    cudaGetSymbolAddress((void**)&a, g_a);

    cudaFuncSetAttribute(qkv_tc, cudaFuncAttributeMaxDynamicSharedMemorySize, GEMM_SMEM);
    cudaFuncSetAttribute(out_tc, cudaFuncAttributeMaxDynamicSharedMemorySize, GEMM_SMEM);
    cudaFuncSetAttribute(attn_mma, cudaFuncAttributeMaxDynamicSharedMemorySize, ATTN_SMEM);

    // 1) operand conversions (pure streaming casts)
    convert_cast<<<SEQ * DIM / 1024, 256>>>(x, a);
    convert_w_cast<<<dim3(DIM * DIM / 1024, 4), 256>>>(Wq, Wk, Wv, Wo);

    // 2) Q/K/V projections (all 1-term fp16, raw-W B operand)
    qkv_tc<<<dim3(DIM / TNN, SEQ / TMM, 3), 256, GEMM_SMEM>>>(bq, bk, bv);

    // 3) attention — GLOBAL heavy-first CTA order: grid(NH, SEQ/QT)
    attn_mma<<<dim3(NH, SEQ / QT), 256, ATTN_SMEM>>>();

    // 4) output projection (1-term)
    out_tc<<<dim3(DIM / TNN, SEQ / TMM), 256, GEMM_SMEM>>>(bo, out);
}

// round 17
// speedup vs baseline: 1.7636x; 1.0127x over previous
#include <cuda_runtime.h>
#include <cuda_fp16.h>
#include <cstdint>
#include <string.h>
#include <math.h>

// Problem constants
#define SEQ 2048
#define DIM 2048
#define NH  16
#define DK  128

// ------------------------------------------------------------------
// Scratch (device globals)
// ------------------------------------------------------------------
__device__ __half g_a[SEQ * DIM];             // A operand (x, then att), fp16
__device__ __half g_w[4u * DIM * DIM];        // W per matrix, RAW [K,N] layout, fp16
__device__ __half g_q[NH * SEQ * DK];         // Q fp16 (1/sqrt(dk) folded at epilogue)
__device__ __half g_k[NH * SEQ * DK];         // K fp16
__device__ __half g_v[NH * SEQ * DK];         // V fp16 (row-major, trans at ldmatrix)

// ------------------------------------------------------------------
// Baseline-PTX helpers (sm_80-level)
// ------------------------------------------------------------------
__device__ __forceinline__ uint32_t smem_u32(const void* p) {
    uint32_t a;
    asm("{ .reg .u64 t; cvta.to.shared.u64 t, %1; cvt.u32.u64 %0, t; }" : "=r"(a) : "l"(p));
    return a;
}

#define CP_ASYNC16(sm, gp) \
    asm volatile("cp.async.cg.shared.global [%0], [%1], 16;" :: "r"(sm), "l"(gp))
#define CP_COMMIT() asm volatile("cp.async.commit_group;" ::: "memory")
#define CP_WAIT1()  asm volatile("cp.async.wait_group 1;" ::: "memory")
#define CP_WAIT0()  asm volatile("cp.async.wait_group 0;" ::: "memory")

#define LDSM_X4(r0, r1, r2, r3, addr) \
    asm volatile("ldmatrix.sync.aligned.m8n8.x4.shared.b16 {%0,%1,%2,%3}, [%4];" \
                 : "=r"(r0), "=r"(r1), "=r"(r2), "=r"(r3) : "r"(addr))

#define LDSM_X4_T(r0, r1, r2, r3, addr) \
    asm volatile("ldmatrix.sync.aligned.m8n8.x4.trans.shared.b16 {%0,%1,%2,%3}, [%4];" \
                 : "=r"(r0), "=r"(r1), "=r"(r2), "=r"(r3) : "r"(addr))

#define MMA16816(c, a, b) \
    asm volatile("mma.sync.aligned.m16n8k16.row.col.f32.f16.f16.f32 " \
                 "{%0,%1,%2,%3}, {%4,%5,%6,%7}, {%8,%9}, {%0,%1,%2,%3};" \
                 : "+f"((c)[0]), "+f"((c)[1]), "+f"((c)[2]), "+f"((c)[3]) \
                 : "r"((a)[0]), "r"((a)[1]), "r"((a)[2]), "r"((a)[3]), \
                   "r"((b)[0]), "r"((b)[1]))

__device__ __forceinline__ uint32_t h2u(__half2 v) {
    uint32_t u; memcpy(&u, &v, 4); return u;
}

// ------------------------------------------------------------------
// Conversion kernel — pure streaming casts, ONE launch:
//   y=0..3: W fp32 -> g_w[y] fp16 (raw layout)
//   y=4   : x fp32 -> g_a fp16
// Same float4 body for all branches (proven convert_w_cast pattern).
// ------------------------------------------------------------------
__global__ __launch_bounds__(256) void convert_all_cast(
    const float* __restrict__ Wq, const float* __restrict__ Wk,
    const float* __restrict__ Wv, const float* __restrict__ Wo,
    const float* __restrict__ x)
{
    int z = blockIdx.y;
    const float* src = (z == 0) ? Wq : (z == 1) ? Wk : (z == 2) ? Wv
                     : (z == 3) ? Wo : x;
    __half* outp = (z < 4) ? (g_w + (size_t)z * DIM * DIM) : g_a;
    size_t i = ((size_t)blockIdx.x * 256 + threadIdx.x) * 4;
    float4 v = *(const float4*)(src + i);
    *(__half2*)(outp + i)     = __halves2half2(__float2half_rn(v.x), __float2half_rn(v.y));
    *(__half2*)(outp + i + 2) = __halves2half2(__float2half_rn(v.z), __float2half_rn(v.w));
}

// ------------------------------------------------------------------
// mma.sync fp16 GEMM (1-term): out = A @ W + bias, W RAW [K,N].
// B fragments via ldmatrix.trans on raw W tiles. CTA 128x128, KC=64,
// cp.async double buffer, one barrier per chunk, 2 CTAs/SM.
// ------------------------------------------------------------------
#define TMM 128
#define TNN 128
#define KC 64
#define NCHUNK (DIM / KC)
#define ASTR 144                     // A row stride (128B payload + pad)
#define BSTR 272                     // B row stride (256B payload + pad)
#define A_TILE (128 * ASTR)          // 18432
#define B_TILE (64 * BSTR)           // 17408
#define OFF_A 0
#define OFF_B A_TILE
#define STAGE_B (A_TILE + B_TILE)    // 35840
#define GEMM_SMEM (2 * STAGE_B)      // 71680

__device__ __forceinline__ void load_chunk(
    uint32_t sbase, const __half* __restrict__ A, const __half* __restrict__ W,
    int row0, int col0, int k0, int tid)
{
    // A: 128 rows x 128B (k-major)
    {
        const int col16 = tid & 7;
        const int rb    = tid >> 3;
        const int kg    = k0 + col16 * 8;
#pragma unroll
        for (int t = 0; t < 4; ++t) {
            int r = rb + t * 32;
            CP_ASYNC16(sbase + OFF_A + r * ASTR + col16 * 16,
                       A + (size_t)(row0 + r) * DIM + kg);
        }
    }
    // B: 64 k-rows x 256B (raw W[K,N] slice)
    {
#pragma unroll
        for (int t = 0; t < 4; ++t) {
            int u = tid + t * 256;
            int r = u >> 4, c16 = u & 15;
            CP_ASYNC16(sbase + OFF_B + r * BSTR + c16 * 16,
                       W + (size_t)(k0 + r) * DIM + col0 + c16 * 8);
        }
    }
}

// mode 0: fp32 [S][DIM]; mode 2: fp16 scatter [H][S][DK]
__device__ __forceinline__ void gemm_tc_body(
    const __half* __restrict__ A, const __half* __restrict__ W,
    const float* __restrict__ bias, float bscale,
    float* __restrict__ outp, __half* __restrict__ ohi, int mode)
{
    extern __shared__ char smg[];
    const int tid  = threadIdx.x;
    const int wid  = tid >> 5;
    const int lane = tid & 31;
    const int row0 = blockIdx.y * TMM;
    const int col0 = blockIdx.x * TNN;
    const int wm   = (wid & 3) * 32;
    const int wn   = (wid >> 2) * 64;
    const uint32_t sb = smem_u32(smg);

    float c[2][8][4];
#pragma unroll
    for (int mt = 0; mt < 2; ++mt)
#pragma unroll
        for (int nt = 0; nt < 8; ++nt)
#pragma unroll
            for (int j = 0; j < 4; ++j) c[mt][nt][j] = 0.0f;

    const uint32_t a_off = (wm + (lane & 15)) * ASTR + (lane >> 4) * 16;
    const uint32_t b_off = ((lane & 7) + ((lane >> 3) & 1) * 8) * BSTR
                         + ((lane >> 4) & 1) * 16 + wn * 2;

    load_chunk(sb, A, W, row0, col0, 0, tid);
    CP_COMMIT();

    for (int ch = 0; ch < NCHUNK; ++ch) {
        CP_WAIT0();
        __syncthreads();
        if (ch + 1 < NCHUNK) {
            load_chunk(sb + ((ch + 1) & 1) * STAGE_B, A, W, row0, col0,
                       (ch + 1) * KC, tid);
            CP_COMMIT();
        }

        const uint32_t stage = sb + (ch & 1) * STAGE_B;
#pragma unroll
        for (int ks = 0; ks < 4; ++ks) {
            uint32_t a[2][4];
#pragma unroll
            for (int mt = 0; mt < 2; ++mt) {
                uint32_t ad = stage + (uint32_t)(mt * 16 * ASTR) + a_off + ks * 32;
                LDSM_X4(a[mt][0], a[mt][1], a[mt][2], a[mt][3], ad + OFF_A);
            }
            uint32_t b[8][2];
#pragma unroll
            for (int pp = 0; pp < 4; ++pp) {
                uint32_t bd = stage + OFF_B + b_off
                            + (uint32_t)(ks * 16 * BSTR) + pp * 32;
                LDSM_X4_T(b[2 * pp][0], b[2 * pp][1],
                          b[2 * pp + 1][0], b[2 * pp + 1][1], bd);
            }
#pragma unroll
            for (int mt = 0; mt < 2; ++mt)
#pragma unroll
                for (int nt = 0; nt < 8; ++nt)
                    MMA16816(c[mt][nt], a[mt], b[nt]);
        }
    }

#pragma unroll
    for (int mt = 0; mt < 2; ++mt) {
#pragma unroll
        for (int nt = 0; nt < 8; ++nt) {
            int cg = col0 + wn + nt * 8 + (lane & 3) * 2;
            float b0 = bias[cg] * bscale;
            float b1 = bias[cg + 1] * bscale;
            int r0 = row0 + wm + mt * 16 + (lane >> 2);
#pragma unroll
            for (int hh = 0; hh < 2; ++hh) {
                int r = r0 + hh * 8;
                float v0 = fmaf(c[mt][nt][2 * hh + 0], bscale, b0);
                float v1 = fmaf(c[mt][nt][2 * hh + 1], bscale, b1);
                if (mode == 0) {
                    float* ob = outp + (size_t)r * DIM + cg;
                    ob[0] = v0; ob[1] = v1;
                } else {
                    int hd = cg >> 7, d0 = cg & 127;
                    size_t base = ((size_t)hd * SEQ + r) * DK + d0;
                    *(__half2*)(ohi + base) =
                        __halves2half2(__float2half_rn(v0), __float2half_rn(v1));
                }
            }
        }
    }
}

__global__ __launch_bounds__(256, 2) void qkv_tc(
    const float* __restrict__ bq, const float* __restrict__ bk, const float* __restrict__ bvv)
{
    int z = blockIdx.z;
    const __half* W = g_w + (size_t)z * DIM * DIM;
    const float* bias = (z == 0) ? bq : (z == 1) ? bk : bvv;
    __half* outp = (z == 0) ? g_q : (z == 1) ? g_k : g_v;
    float bscale = (z == 0) ? 0.08838834764831845f : 1.0f;
    gemm_tc_body(g_a, W, bias, bscale, nullptr, outp, 2);
}

__global__ __launch_bounds__(256, 2) void out_tc(const float* __restrict__ bo, float* __restrict__ out)
{
    gemm_tc_body(g_a, g_w + (size_t)3 * DIM * DIM, bo, 1.0f, out, nullptr, 0);
}

// ------------------------------------------------------------------
// mma.sync fp16 causal flash attention — cross-tile software pipeline.
// GLOBAL heavy-first scheduling: grid(NH, SEQ/QT), head on x (fast),
// q-tile weight on y => 148 heaviest CTAs dispatch first chip-wide.
// ------------------------------------------------------------------
#define QT 128
#define KT 64
#define QSTR 272                      // 256B payload + 16B pad
#define QB 0                          // Q: 128 rows x QSTR = 34816
#define QB_TOT (128 * QSTR)           // 34816
#define SK 0                          // K: 64 rows x QSTR = 17408
#define SV (64 * QSTR)                // V: 64 rows x QSTR = 17408
#define STAGE_SZ (2 * 64 * QSTR)      // 34816 per KV stage
#define NSTAGE 4
#define ATTN_SMEM (QB_TOT + NSTAGE * STAGE_SZ)   // 174080

__device__ __forceinline__ void attn_load_kv(uint32_t st, int h, int kv0, int tid)
{
    const __half* kh = g_k + ((size_t)h * SEQ + kv0) * DK;
    const __half* vh = g_v + ((size_t)h * SEQ + kv0) * DK;
    int r = tid >> 2;                 // 0..63
#pragma unroll
    for (int i = 0; i < 4; ++i) {
        int u = (tid & 3) * 4 + i;
        CP_ASYNC16(st + SK + r * QSTR + u * 16, kh + (size_t)r * DK + u * 8);
        CP_ASYNC16(st + SV + r * QSTR + u * 16, vh + (size_t)r * DK + u * 8);
    }
}

__global__ __launch_bounds__(256, 1) void attn_mma()
{
    extern __shared__ char sma[];
    const uint32_t sb = smem_u32(sma);
    const int tid  = threadIdx.x;
    const int wid  = tid >> 5;
    const int lane = tid & 31;
    const int h    = blockIdx.x;           // head on FAST axis
    const int qi   = 15 - blockIdx.y;      // heavy q-tiles dispatch first globally
    const int q0   = qi * QT;
    const int ntiles = 2 * (qi + 1);

    // prologue: Q tile + stage 0 KV
    {
        const __half* qh = g_q + ((size_t)h * SEQ + q0) * DK;
        int r = tid >> 1;
#pragma unroll
        for (int i = 0; i < 8; ++i) {
            int u = (tid & 1) * 8 + i;
            CP_ASYNC16(sb + QB + r * QSTR + u * 16, qh + (size_t)r * DK + u * 8);
        }
        attn_load_kv(sb + QB_TOT, h, 0, tid);
        CP_COMMIT();
    }

    // per-lane fragment address components
    const uint32_t a_off  = (wid * 16 + (lane & 15)) * QSTR + (lane >> 4) * 16;
    const uint32_t bk_off = ((lane & 7) + ((lane >> 4) & 1) * 8) * QSTR + ((lane >> 3) & 1) * 16;
    const uint32_t bv_off = ((lane & 7) + ((lane >> 3) & 1) * 8) * QSTR + ((lane >> 4) & 1) * 16;

    const int row0_abs = q0 + wid * 16 + (lane >> 2);
    const int rowmax   = q0 + wid * 16 + 15;

    float o[16][4];
#pragma unroll
    for (int nt = 0; nt < 16; ++nt)
#pragma unroll
        for (int j = 0; j < 4; ++j) o[nt][j] = 0.0f;
    float m0 = -1e4f, m1 = -1e4f, l0 = 0.0f, l1 = 0.0f;

    uint32_t qa[8][4];
    uint32_t aph[4][4];
    uint32_t prev_st = 0;
    int have_prev = 0;

    for (int jt = 0; jt < ntiles; ++jt) {
        if (jt + 1 < ntiles) {
            attn_load_kv(sb + QB_TOT + ((jt + 1) & (NSTAGE - 1)) * STAGE_SZ,
                         h, (jt + 1) * KT, tid);
            CP_COMMIT();
            CP_WAIT1();
        } else {
            CP_WAIT0();
        }
        __syncthreads();   // single barrier per tile (4-stage ring)

        if (jt == 0) {
#pragma unroll
            for (int ks = 0; ks < 8; ++ks)
                LDSM_X4(qa[ks][0], qa[ks][1], qa[ks][2], qa[ks][3],
                        sb + QB + a_off + ks * 32);
        }

        const int kv0 = jt * KT;
        const int active = (kv0 <= rowmax);
        const uint32_t st = sb + QB_TOT + (jt & (NSTAGE - 1)) * STAGE_SZ;

        // ---- issue QK_jt (Q from registers) ----
        float s[8][4];
        if (active) {
#pragma unroll
            for (int nt = 0; nt < 8; ++nt)
#pragma unroll
                for (int j = 0; j < 4; ++j) s[nt][j] = 0.0f;
#pragma unroll
            for (int ks = 0; ks < 8; ++ks) {
                uint32_t bh[8][2];
#pragma unroll
                for (int q = 0; q < 4; ++q) {
                    uint32_t ba = st + SK + bk_off + q * (16 * QSTR) + ks * 32;
                    LDSM_X4(bh[2 * q][0], bh[2 * q][1], bh[2 * q + 1][0], bh[2 * q + 1][1], ba);
                }
#pragma unroll
                for (int nt = 0; nt < 8; ++nt) MMA16816(s[nt], qa[ks], bh[nt]);
            }
        }

        // ---- deferred PV_{jt-1}: overlaps the QK->softmax dependency ----
        if (have_prev) {
#pragma unroll
            for (int kp = 0; kp < 4; ++kp) {
#pragma unroll
                for (int p = 0; p < 8; ++p) {
                    uint32_t r0, r1, r2, r3;
                    LDSM_X4_T(r0, r1, r2, r3,
                              prev_st + SV + bv_off + kp * (16 * QSTR) + p * 32);
                    uint32_t b01[2] = {r0, r1};
                    uint32_t b23[2] = {r2, r3};
                    MMA16816(o[2 * p + 0], aph[kp], b01);
                    MMA16816(o[2 * p + 1], aph[kp], b23);
                }
            }
            have_prev = 0;
        }

        if (active) {
            // ---- causal mask ----
            if (kv0 + KT - 1 > q0 + wid * 16) {
#pragma unroll
                for (int nt = 0; nt < 8; ++nt) {
                    int cb = kv0 + nt * 8 + (lane & 3) * 2;
#pragma unroll
                    for (int j = 0; j < 4; ++j) {
                        int col = cb + (j & 1);
                        int row = row0_abs + (j >> 1) * 8;
                        if (col > row) s[nt][j] = -1e30f;
                    }
                }
            }

            // ---- online softmax ----
            float tm0 = -1e30f, tm1 = -1e30f;
#pragma unroll
            for (int nt = 0; nt < 8; ++nt) {
                tm0 = fmaxf(tm0, fmaxf(s[nt][0], s[nt][1]));
                tm1 = fmaxf(tm1, fmaxf(s[nt][2], s[nt][3]));
            }
            tm0 = fmaxf(tm0, __shfl_xor_sync(0xffffffffu, tm0, 1));
            tm0 = fmaxf(tm0, __shfl_xor_sync(0xffffffffu, tm0, 2));
            tm1 = fmaxf(tm1, __shfl_xor_sync(0xffffffffu, tm1, 1));
            tm1 = fmaxf(tm1, __shfl_xor_sync(0xffffffffu, tm1, 2));
            float mn0 = fmaxf(fmaxf(m0, tm0), -1e4f);
            float mn1 = fmaxf(fmaxf(m1, tm1), -1e4f);
            float al0 = __expf(m0 - mn0), al1 = __expf(m1 - mn1);
            m0 = mn0; m1 = mn1;
            float ls0 = 0.0f, ls1 = 0.0f;
#pragma unroll
            for (int nt = 0; nt < 8; ++nt) {
                s[nt][0] = __expf(s[nt][0] - mn0);
                s[nt][1] = __expf(s[nt][1] - mn0);
                s[nt][2] = __expf(s[nt][2] - mn1);
                s[nt][3] = __expf(s[nt][3] - mn1);
                ls0 += s[nt][0] + s[nt][1];
                ls1 += s[nt][2] + s[nt][3];
            }
            l0 = l0 * al0 + ls0;
            l1 = l1 * al1 + ls1;
#pragma unroll
            for (int nt = 0; nt < 16; ++nt) {
                o[nt][0] *= al0; o[nt][1] *= al0;
                o[nt][2] *= al1; o[nt][3] *= al1;
            }

            // ---- pack P_jt into PV A-frags (fp16, 1-term), defer the MMAs ----
#pragma unroll
            for (int pr = 0; pr < 4; ++pr) {
#pragma unroll
                for (int half = 0; half < 2; ++half) {
                    int nt = 2 * pr + half;
                    aph[pr][2 * half + 0] =
                        h2u(__halves2half2(__float2half_rn(s[nt][0]),
                                           __float2half_rn(s[nt][1])));
                    aph[pr][2 * half + 1] =
                        h2u(__halves2half2(__float2half_rn(s[nt][2]),
                                           __float2half_rn(s[nt][3])));
                }
            }
            prev_st = st;
            have_prev = 1;
        }
    }

    // ---- drain last deferred PV ----
    if (have_prev) {
#pragma unroll
        for (int kp = 0; kp < 4; ++kp) {
#pragma unroll
            for (int p = 0; p < 8; ++p) {
                uint32_t r0, r1, r2, r3;
                LDSM_X4_T(r0, r1, r2, r3,
                          prev_st + SV + bv_off + kp * (16 * QSTR) + p * 32);
                uint32_t b01[2] = {r0, r1};
                uint32_t b23[2] = {r2, r3};
                MMA16816(o[2 * p + 0], aph[kp], b01);
                MMA16816(o[2 * p + 1], aph[kp], b23);
            }
        }
    }

    // ---- epilogue: normalize, cast fp16, write att into A operand ----
    l0 += __shfl_xor_sync(0xffffffffu, l0, 1);
    l0 += __shfl_xor_sync(0xffffffffu, l0, 2);
    l1 += __shfl_xor_sync(0xffffffffu, l1, 1);
    l1 += __shfl_xor_sync(0xffffffffu, l1, 2);
    float inv0 = 1.0f / l0, inv1 = 1.0f / l1;

    const int r0 = row0_abs;
    const int r1 = row0_abs + 8;
#pragma unroll
    for (int nt = 0; nt < 16; ++nt) {
        int d = h * DK + nt * 8 + (lane & 3) * 2;
        *(__half2*)(g_a + (size_t)r0 * DIM + d) =
            __halves2half2(__float2half_rn(o[nt][0] * inv0),
                           __float2half_rn(o[nt][1] * inv0));
        *(__half2*)(g_a + (size_t)r1 * DIM + d) =
            __halves2half2(__float2half_rn(o[nt][2] * inv1),
                           __float2half_rn(o[nt][3] * inv1));
    }
}

// ------------------------------------------------------------------
// Launch
// ------------------------------------------------------------------
extern "C" void kernel_launch(void* const* d_in, const int* in_sizes, int n_in,
                              void* d_out, int out_size)
{
    const float* x  = (const float*)d_in[0];
    const float* Wq = (const float*)d_in[1];
    const float* bq = (const float*)d_in[2];
    const float* Wk = (const float*)d_in[3];
    const float* bk = (const float*)d_in[4];
    const float* Wv = (const float*)d_in[5];
    const float* bv = (const float*)d_in[6];
    const float* Wo = (const float*)d_in[7];
    const float* bo = (const float*)d_in[8];
    float* out = (float*)d_out;

    cudaFuncSetAttribute(qkv_tc, cudaFuncAttributeMaxDynamicSharedMemorySize, GEMM_SMEM);
    cudaFuncSetAttribute(out_tc, cudaFuncAttributeMaxDynamicSharedMemorySize, GEMM_SMEM);
    cudaFuncSetAttribute(attn_mma, cudaFuncAttributeMaxDynamicSharedMemorySize, ATTN_SMEM);

    // 1) all operand conversions in ONE float4 streaming launch
    convert_all_cast<<<dim3(DIM * DIM / 1024, 5), 256>>>(Wq, Wk, Wv, Wo, x);

    // 2) Q/K/V projections (all 1-term fp16, raw-W B operand)
    qkv_tc<<<dim3(DIM / TNN, SEQ / TMM, 3), 256, GEMM_SMEM>>>(bq, bk, bv);

    // 3) attention — GLOBAL heavy-first CTA order: grid(NH, SEQ/QT)
    attn_mma<<<dim3(NH, SEQ / QT), 256, ATTN_SMEM>>>();

    // 4) output projection (1-term)
    out_tc<<<dim3(DIM / TNN, SEQ / TMM), 256, GEMM_SMEM>>>(bo, out);
}